// round 1
// baseline (speedup 1.0000x reference)
#include <cuda_runtime.h>
#include <cstdint>

// ---------------------------------------------------------------------------
// SelfAttentionV2: QKV = X@W^T + b ; S = softmax(Q K^T / 32) ; O = S V
// X [4,4096,1024] f32, W [3072,1024] f32, b [3072] f32 -> O [4,4096,1024] f32
//
// Pipeline (4 launches, all tf32 tensor-core mma):
//   1) gemm_tf32 mode 0 : QKV projection, routes Q,K row-major, V transposed
//   2) gemm_tf32 mode 1 : S = Q K^T * (1/32)   (batched over 4)
//   3) softmax_rows     : row softmax in-place on S
//   4) gemm_tf32 mode 1 : O = S @ Vt^T         (batched over 4)
// ---------------------------------------------------------------------------

#define NBATCH 4
#define SEQ    4096
#define DIMD   1024

// Scratch (device-global arrays: allowed; no cudaMalloc anywhere)
__device__ float g_q [NBATCH * SEQ * DIMD];          // 64 MB
__device__ float g_k [NBATCH * SEQ * DIMD];          // 64 MB
__device__ float g_vt[NBATCH * DIMD * SEQ];          // 64 MB (V transposed: [b][d][s])
__device__ float g_s [67108864];                     // 256 MB scores [b][q][k]

__device__ __forceinline__ uint32_t f2tf(float f) {
    uint32_t u;
    asm("cvt.rna.tf32.f32 %0, %1;" : "=r"(u) : "f"(f));
    return u;
}

__device__ __forceinline__ void mma_tf32(float c[4], const uint32_t a[4], const uint32_t b[2]) {
    asm volatile(
        "mma.sync.aligned.m16n8k8.row.col.f32.tf32.tf32.f32 "
        "{%0,%1,%2,%3}, {%4,%5,%6,%7}, {%8,%9}, {%0,%1,%2,%3};"
        : "+f"(c[0]), "+f"(c[1]), "+f"(c[2]), "+f"(c[3])
        : "r"(a[0]), "r"(a[1]), "r"(a[2]), "r"(a[3]), "r"(b[0]), "r"(b[1]));
}

// C[M,N] = A[M,K] @ B[N,K]^T  (both operands K-major). Tiles 128x128x32.
// 256 threads = 8 warps, warp tile 64(m) x 32(n), mma m16n8k8 tf32.
// mode 0: QKV epilogue (bias + route to g_q/g_k/g_vt), batchless (M = 16384)
// mode 1: C[z] [row*N+col] = acc * scale, batched via blockIdx.z
__global__ __launch_bounds__(256) void gemm_tf32(
    const float* __restrict__ A, const float* __restrict__ B,
    const float* __restrict__ bias, float* __restrict__ C,
    int K, int N, int lda, int ldb,
    long long strideA, long long strideB, long long strideC,
    int mode, float scale)
{
    __shared__ uint32_t sA[128][33];
    __shared__ uint32_t sB[128][33];

    const int tid  = threadIdx.x;
    const int warp = tid >> 5;
    const int lane = tid & 31;
    const int wm   = warp & 1;    // warp row (0..1) -> m offset wm*64
    const int wn   = warp >> 1;   // warp col (0..3) -> n offset wn*32
    const int g    = lane >> 2;   // group id
    const int t    = lane & 3;    // thread-in-group

    const float* Ab = A + strideA * blockIdx.z + (long long)blockIdx.y * 128 * lda;
    const float* Bb = B + strideB * blockIdx.z + (long long)blockIdx.x * 128 * ldb;

    float acc[4][4][4] = {};

    for (int k0 = 0; k0 < K; k0 += 32) {
        __syncthreads();
        // Load 128x32 A-tile and 128x32 B-tile, convert to tf32.
        #pragma unroll
        for (int i = 0; i < 4; i++) {
            int idx = tid + i * 256;
            int r   = idx >> 3;
            int c   = (idx & 7) << 2;
            float4 va = *reinterpret_cast<const float4*>(Ab + (long long)r * lda + k0 + c);
            sA[r][c + 0] = f2tf(va.x); sA[r][c + 1] = f2tf(va.y);
            sA[r][c + 2] = f2tf(va.z); sA[r][c + 3] = f2tf(va.w);
            float4 vb = *reinterpret_cast<const float4*>(Bb + (long long)r * ldb + k0 + c);
            sB[r][c + 0] = f2tf(vb.x); sB[r][c + 1] = f2tf(vb.y);
            sB[r][c + 2] = f2tf(vb.z); sB[r][c + 3] = f2tf(vb.w);
        }
        __syncthreads();

        #pragma unroll
        for (int kk = 0; kk < 4; kk++) {
            const int kb = kk * 8;
            uint32_t af[4][4];
            #pragma unroll
            for (int mt = 0; mt < 4; mt++) {
                int r = wm * 64 + mt * 16 + g;
                af[mt][0] = sA[r    ][kb + t    ];
                af[mt][1] = sA[r + 8][kb + t    ];
                af[mt][2] = sA[r    ][kb + t + 4];
                af[mt][3] = sA[r + 8][kb + t + 4];
            }
            uint32_t bf[4][2];
            #pragma unroll
            for (int nt = 0; nt < 4; nt++) {
                int n = wn * 32 + nt * 8 + g;
                bf[nt][0] = sB[n][kb + t    ];
                bf[nt][1] = sB[n][kb + t + 4];
            }
            #pragma unroll
            for (int mt = 0; mt < 4; mt++)
                #pragma unroll
                for (int nt = 0; nt < 4; nt++)
                    mma_tf32(acc[mt][nt], af[mt], bf[nt]);
        }
    }

    // Epilogue
    #pragma unroll
    for (int mt = 0; mt < 4; mt++) {
        #pragma unroll
        for (int nt = 0; nt < 4; nt++) {
            int row = blockIdx.y * 128 + wm * 64 + mt * 16 + g;
            int col = blockIdx.x * 128 + wn * 32 + nt * 8 + t * 2;
            float* cc = acc[mt][nt];
            if (mode == 0) {
                #pragma unroll
                for (int e = 0; e < 4; e++) {
                    int r  = row + ((e >= 2) ? 8 : 0);
                    int c2 = col + (e & 1);
                    float v = cc[e] + bias[c2];
                    int b = r >> 12;          // row / 4096
                    int s = r & 4095;
                    long long base = (long long)b << 22;   // b * 4096*1024
                    if (c2 < 1024)       g_q [base + (long long)s * 1024 + c2] = v;
                    else if (c2 < 2048)  g_k [base + (long long)s * 1024 + (c2 - 1024)] = v;
                    else                 g_vt[base + (long long)(c2 - 2048) * 4096 + s] = v;
                }
            } else {
                float* Cp = C + strideC * blockIdx.z;
                Cp[(long long)(row    ) * N + col    ] = cc[0] * scale;
                Cp[(long long)(row    ) * N + col + 1] = cc[1] * scale;
                Cp[(long long)(row + 8) * N + col    ] = cc[2] * scale;
                Cp[(long long)(row + 8) * N + col + 1] = cc[3] * scale;
            }
        }
    }
}

// One block per row of 4096 floats; in-place softmax.
__global__ __launch_bounds__(256) void softmax_rows(float* __restrict__ S)
{
    float* p = S + (long long)blockIdx.x * 4096;
    const int tid  = threadIdx.x;
    const int warp = tid >> 5;
    const int lane = tid & 31;
    __shared__ float red[8];

    float4 v[4];
    float m = -3.4e38f;
    #pragma unroll
    for (int i = 0; i < 4; i++) {
        v[i] = reinterpret_cast<float4*>(p)[tid + i * 256];
        m = fmaxf(m, fmaxf(fmaxf(v[i].x, v[i].y), fmaxf(v[i].z, v[i].w)));
    }
    #pragma unroll
    for (int o = 16; o > 0; o >>= 1) m = fmaxf(m, __shfl_xor_sync(0xffffffffu, m, o));
    if (lane == 0) red[warp] = m;
    __syncthreads();
    m = red[0];
    #pragma unroll
    for (int i = 1; i < 8; i++) m = fmaxf(m, red[i]);
    __syncthreads();

    float sum = 0.f;
    #pragma unroll
    for (int i = 0; i < 4; i++) {
        v[i].x = expf(v[i].x - m); v[i].y = expf(v[i].y - m);
        v[i].z = expf(v[i].z - m); v[i].w = expf(v[i].w - m);
        sum += v[i].x + v[i].y + v[i].z + v[i].w;
    }
    #pragma unroll
    for (int o = 16; o > 0; o >>= 1) sum += __shfl_xor_sync(0xffffffffu, sum, o);
    if (lane == 0) red[warp] = sum;
    __syncthreads();
    sum = red[0] + red[1] + red[2] + red[3] + red[4] + red[5] + red[6] + red[7];

    const float inv = 1.0f / sum;
    #pragma unroll
    for (int i = 0; i < 4; i++) {
        v[i].x *= inv; v[i].y *= inv; v[i].z *= inv; v[i].w *= inv;
        reinterpret_cast<float4*>(p)[tid + i * 256] = v[i];
    }
}

extern "C" void kernel_launch(void* const* d_in, const int* in_sizes, int n_in,
                              void* d_out, int out_size)
{
    const float* X    = (const float*)d_in[0];
    const float* W    = (const float*)d_in[1];
    const float* bias = (const float*)d_in[2];
    float*       out  = (float*)d_out;

    float *q, *k, *vt, *s;
    cudaGetSymbolAddress((void**)&q,  g_q);
    cudaGetSymbolAddress((void**)&k,  g_k);
    cudaGetSymbolAddress((void**)&vt, g_vt);
    cudaGetSymbolAddress((void**)&s,  g_s);

    // 1) QKV projection: [16384,1024] @ [3072,1024]^T, routed epilogue
    gemm_tf32<<<dim3(24, 128, 1), 256>>>(X, W, bias, nullptr,
                                         1024, 3072, 1024, 1024,
                                         0, 0, 0, /*mode=*/0, 1.0f);
    // 2) Scores: per-batch [4096,1024] @ [4096,1024]^T * (1/32)
    gemm_tf32<<<dim3(32, 32, 4), 256>>>(q, k, nullptr, s,
                                        1024, 4096, 1024, 1024,
                                        1LL << 22, 1LL << 22, 16777216LL,
                                        /*mode=*/1, 0.03125f);
    // 3) Row softmax over 16384 rows of 4096
    softmax_rows<<<16384, 256>>>(s);
    // 4) Output: per-batch [4096,4096] @ [1024,4096]^T
    gemm_tf32<<<dim3(8, 32, 4), 256>>>(s, vt, nullptr, out,
                                       4096, 1024, 4096, 4096,
                                       16777216LL, 1LL << 22, 4194304LL,
                                       /*mode=*/1, 1.0f);
}

// round 2
// speedup vs baseline: 1.4998x; 1.4998x over previous
#include <cuda_runtime.h>
#include <cstdint>

// ---------------------------------------------------------------------------
// SelfAttentionV2: QKV = X@W^T + b ; S = softmax(Q K^T / 32) ; O = S V
// X [4,4096,1024] f32, W [3072,1024] f32, b [3072] f32 -> O [4,4096,1024] f32
//
// Round 2: tf32 mma.sync GEMM with fragment-order (quad) smem layout
// (vectorized LDS.128 fragment reads), double-buffered smem + register
// prefetch (1 sync/iter). 1/32 folded into Q. __expf softmax.
// ---------------------------------------------------------------------------

#define NBATCH 4
#define SEQ    4096
#define DIMD   1024

__device__ float g_q [NBATCH * SEQ * DIMD];          // 64 MB (pre-scaled by 1/32)
__device__ float g_k [NBATCH * SEQ * DIMD];          // 64 MB
__device__ float g_vt[NBATCH * DIMD * SEQ];          // 64 MB (V transposed [b][d][s])
__device__ float g_s [67108864];                     // 256 MB scores [b][q][k]

__device__ __forceinline__ uint32_t f2tf(float f) {
    uint32_t u;
    asm("cvt.rna.tf32.f32 %0, %1;" : "=r"(u) : "f"(f));
    return u;
}

__device__ __forceinline__ void mma_tf32(float c[4], const uint32_t a[4], const uint32_t b[2]) {
    asm volatile(
        "mma.sync.aligned.m16n8k8.row.col.f32.tf32.tf32.f32 "
        "{%0,%1,%2,%3}, {%4,%5,%6,%7}, {%8,%9}, {%0,%1,%2,%3};"
        : "+f"(c[0]), "+f"(c[1]), "+f"(c[2]), "+f"(c[3])
        : "r"(a[0]), "r"(a[1]), "r"(a[2]), "r"(a[3]), "r"(b[0]), "r"(b[1]));
}

// Quad layout: tile 128(rows) x 32(k) stored so each thread's 4-reg MMA
// fragment is one 16B LDS. quad(rb,kk,g,t) holds rows {rb*16+g, rb*16+8+g}
// x cols {kk*8+t, kk*8+t+4}, slot = m_hi + 2*k_hi. Quads placed at
// index ((rb*4+kk)*8+g)*4 + (t^kk)  (XOR de-conflicts the fill stores).
// Words per tile: 4096 (16 KB).

// C[M,N] = A[M,K] @ B[N,K]^T, both K-major. CTA tile 128x128x32, 8 warps,
// warp tile 64(m)x32(n), mma m16n8k8 tf32, double-buffered smem.
// mode 0: QKV epilogue (bias + route Q(scaled)/K/Vt), mode 1: C = acc*scale.
__global__ __launch_bounds__(256) void gemm_tf32(
    const float* __restrict__ A, const float* __restrict__ B,
    const float* __restrict__ bias, float* __restrict__ C,
    int K, int N, int lda, int ldb,
    long long strideA, long long strideB, long long strideC,
    int mode, float scale)
{
    extern __shared__ uint32_t smem[];   // [2][A:4096 | B:4096] = 64 KB

    const int tid  = threadIdx.x;
    const int warp = tid >> 5;
    const int lane = tid & 31;
    const int wm   = warp & 1;    // m offset wm*64
    const int wn   = warp >> 1;   // n offset wn*32
    const int g    = lane >> 2;
    const int t    = lane & 3;

    const float* Ab = A + strideA * blockIdx.z + (long long)blockIdx.y * 128 * lda;
    const float* Bb = B + strideB * blockIdx.z + (long long)blockIdx.x * 128 * ldb;

    // Per-thread fill coordinates (4 float4 per operand per iter)
    int fr[4], fc[4];
    long long offA[4], offB[4];
    #pragma unroll
    for (int i = 0; i < 4; i++) {
        int idx = tid + i * 256;
        fr[i] = idx >> 3;
        fc[i] = (idx & 7) << 2;
        offA[i] = (long long)fr[i] * lda + fc[i];
        offB[i] = (long long)fr[i] * ldb + fc[i];
    }

    float acc[4][4][4] = {};
    float4 pa[4], pb[4];

    // Prologue: prefetch tile k0=0
    #pragma unroll
    for (int i = 0; i < 4; i++) {
        pa[i] = *reinterpret_cast<const float4*>(Ab + offA[i]);
        pb[i] = *reinterpret_cast<const float4*>(Bb + offB[i]);
    }

    int buf = 0;
    for (int k0 = 0; k0 < K; k0 += 32) {
        uint32_t* sa = smem + buf * 8192;
        uint32_t* sb = sa + 4096;

        // Scatter-store prefetched regs (cvt to tf32) into quad layout
        #pragma unroll
        for (int i = 0; i < 4; i++) {
            int r = fr[i], c = fc[i];
            int kk  = c >> 3;
            int khi = (c >> 2) & 1;
            int base = ((((r >> 4) * 4 + kk) * 8 + (r & 7)) << 4) + ((r >> 3) & 1) + (khi << 1);
            uint32_t* da = sa + base;
            da[((0 ^ kk) << 2)] = f2tf(pa[i].x);
            da[((1 ^ kk) << 2)] = f2tf(pa[i].y);
            da[((2 ^ kk) << 2)] = f2tf(pa[i].z);
            da[((3 ^ kk) << 2)] = f2tf(pa[i].w);
            uint32_t* db = sb + base;
            db[((0 ^ kk) << 2)] = f2tf(pb[i].x);
            db[((1 ^ kk) << 2)] = f2tf(pb[i].y);
            db[((2 ^ kk) << 2)] = f2tf(pb[i].z);
            db[((3 ^ kk) << 2)] = f2tf(pb[i].w);
        }
        __syncthreads();

        // Prefetch next tile while computing this one
        if (k0 + 32 < K) {
            #pragma unroll
            for (int i = 0; i < 4; i++) {
                pa[i] = *reinterpret_cast<const float4*>(Ab + offA[i] + k0 + 32);
                pb[i] = *reinterpret_cast<const float4*>(Bb + offB[i] + k0 + 32);
            }
        }

        #pragma unroll
        for (int kk = 0; kk < 4; kk++) {
            const int tx = (t ^ kk) << 2;
            uint32_t af[4][4];
            #pragma unroll
            for (int mt = 0; mt < 4; mt++) {
                uint4 v = *reinterpret_cast<const uint4*>(
                    sa + ((((wm * 4 + mt) * 4 + kk) * 8 + g) << 4) + tx);
                af[mt][0] = v.x; af[mt][1] = v.y; af[mt][2] = v.z; af[mt][3] = v.w;
            }
            uint32_t bf[4][2];
            #pragma unroll
            for (int p = 0; p < 2; p++) {
                uint4 v = *reinterpret_cast<const uint4*>(
                    sb + ((((wn * 2 + p) * 4 + kk) * 8 + g) << 4) + tx);
                bf[2 * p][0] = v.x; bf[2 * p + 1][0] = v.y;
                bf[2 * p][1] = v.z; bf[2 * p + 1][1] = v.w;
            }
            #pragma unroll
            for (int mt = 0; mt < 4; mt++)
                #pragma unroll
                for (int nt = 0; nt < 4; nt++)
                    mma_tf32(acc[mt][nt], af[mt], bf[nt]);
        }
        buf ^= 1;
    }

    // Epilogue
    #pragma unroll
    for (int mt = 0; mt < 4; mt++) {
        #pragma unroll
        for (int nt = 0; nt < 4; nt++) {
            int row = blockIdx.y * 128 + wm * 64 + mt * 16 + g;
            int col = blockIdx.x * 128 + wn * 32 + nt * 8 + t * 2;
            float* cc = acc[mt][nt];
            if (mode == 0) {
                #pragma unroll
                for (int e = 0; e < 4; e++) {
                    int r  = row + ((e >= 2) ? 8 : 0);
                    int c2 = col + (e & 1);
                    float v = cc[e] + bias[c2];
                    int b = r >> 12;
                    int s = r & 4095;
                    long long base = (long long)b << 22;
                    if (c2 < 1024)       g_q [base + (long long)s * 1024 + c2] = v * 0.03125f;
                    else if (c2 < 2048)  g_k [base + (long long)s * 1024 + (c2 - 1024)] = v;
                    else                 g_vt[base + (long long)(c2 - 2048) * 4096 + s] = v;
                }
            } else {
                float* Cp = C + strideC * blockIdx.z;
                Cp[(long long)(row    ) * N + col    ] = cc[0] * scale;
                Cp[(long long)(row    ) * N + col + 1] = cc[1] * scale;
                Cp[(long long)(row + 8) * N + col    ] = cc[2] * scale;
                Cp[(long long)(row + 8) * N + col + 1] = cc[3] * scale;
            }
        }
    }
}

// One block per row of 4096 floats; in-place softmax.
__global__ __launch_bounds__(256) void softmax_rows(float* __restrict__ S)
{
    float* p = S + (long long)blockIdx.x * 4096;
    const int tid  = threadIdx.x;
    const int warp = tid >> 5;
    const int lane = tid & 31;
    __shared__ float red[8];

    float4 v[4];
    float m = -3.4e38f;
    #pragma unroll
    for (int i = 0; i < 4; i++) {
        v[i] = reinterpret_cast<float4*>(p)[tid + i * 256];
        m = fmaxf(m, fmaxf(fmaxf(v[i].x, v[i].y), fmaxf(v[i].z, v[i].w)));
    }
    #pragma unroll
    for (int o = 16; o > 0; o >>= 1) m = fmaxf(m, __shfl_xor_sync(0xffffffffu, m, o));
    if (lane == 0) red[warp] = m;
    __syncthreads();
    m = red[0];
    #pragma unroll
    for (int i = 1; i < 8; i++) m = fmaxf(m, red[i]);
    __syncthreads();

    float sum = 0.f;
    #pragma unroll
    for (int i = 0; i < 4; i++) {
        v[i].x = __expf(v[i].x - m); v[i].y = __expf(v[i].y - m);
        v[i].z = __expf(v[i].z - m); v[i].w = __expf(v[i].w - m);
        sum += v[i].x + v[i].y + v[i].z + v[i].w;
    }
    #pragma unroll
    for (int o = 16; o > 0; o >>= 1) sum += __shfl_xor_sync(0xffffffffu, sum, o);
    if (lane == 0) red[warp] = sum;
    __syncthreads();
    sum = red[0] + red[1] + red[2] + red[3] + red[4] + red[5] + red[6] + red[7];

    const float inv = 1.0f / sum;
    #pragma unroll
    for (int i = 0; i < 4; i++) {
        v[i].x *= inv; v[i].y *= inv; v[i].z *= inv; v[i].w *= inv;
        reinterpret_cast<float4*>(p)[tid + i * 256] = v[i];
    }
}

extern "C" void kernel_launch(void* const* d_in, const int* in_sizes, int n_in,
                              void* d_out, int out_size)
{
    const float* X    = (const float*)d_in[0];
    const float* W    = (const float*)d_in[1];
    const float* bias = (const float*)d_in[2];
    float*       out  = (float*)d_out;

    float *q, *k, *vt, *s;
    cudaGetSymbolAddress((void**)&q,  g_q);
    cudaGetSymbolAddress((void**)&k,  g_k);
    cudaGetSymbolAddress((void**)&vt, g_vt);
    cudaGetSymbolAddress((void**)&s,  g_s);

    static int smem_set = 0;
    if (!smem_set) {
        cudaFuncSetAttribute(gemm_tf32, cudaFuncAttributeMaxDynamicSharedMemorySize, 65536);
        smem_set = 1;
    }

    // 1) QKV projection: [16384,1024] @ [3072,1024]^T, routed epilogue
    gemm_tf32<<<dim3(24, 128, 1), 256, 65536>>>(X, W, bias, nullptr,
                                                1024, 3072, 1024, 1024,
                                                0, 0, 0, /*mode=*/0, 1.0f);
    // 2) Scores: per-batch [4096,1024] @ [4096,1024]^T (1/32 folded into Q)
    gemm_tf32<<<dim3(32, 32, 4), 256, 65536>>>(q, k, nullptr, s,
                                               1024, 4096, 1024, 1024,
                                               1LL << 22, 1LL << 22, 16777216LL,
                                               /*mode=*/1, 1.0f);
    // 3) Row softmax over 16384 rows of 4096
    softmax_rows<<<16384, 256>>>(s);
    // 4) Output: per-batch [4096,4096] @ [1024,4096]^T
    gemm_tf32<<<dim3(8, 32, 4), 256, 65536>>>(s, vt, nullptr, out,
                                              4096, 1024, 4096, 4096,
                                              16777216LL, 1LL << 22, 4194304LL,
                                              /*mode=*/1, 1.0f);
}

// round 4
// speedup vs baseline: 1.9779x; 1.3188x over previous
#include <cuda_runtime.h>
#include <cstdint>

// ---------------------------------------------------------------------------
// SelfAttentionV2: mma.sync tf32 pipeline, round 4.
// CTA tile 128(M)x256(N)x32(K), 8 warps, warp tile 64x64, quad smem layout
// with conflict-free fill, no mainloop cvt (operands pre-rounded to tf32).
// ---------------------------------------------------------------------------

__device__ float g_x [16777216];   // rounded X
__device__ float g_w [ 3145728];   // rounded W
__device__ float g_q [16777216];   // rounded, pre-scaled 1/32
__device__ float g_k [16777216];   // rounded
__device__ float g_vt[16777216];   // rounded, [b][d][s]
__device__ float g_s [67108864];   // scores [b][q][k]; rounded after softmax

__device__ __forceinline__ uint32_t f2tf(float f) {
    uint32_t u;
    asm("cvt.rna.tf32.f32 %0, %1;" : "=r"(u) : "f"(f));
    return u;
}
__device__ __forceinline__ float rtf(float f) { return __uint_as_float(f2tf(f)); }

__device__ __forceinline__ void mma_tf32(float c[4], const uint32_t a[4], const uint32_t b[2]) {
    asm volatile(
        "mma.sync.aligned.m16n8k8.row.col.f32.tf32.tf32.f32 "
        "{%0,%1,%2,%3}, {%4,%5,%6,%7}, {%8,%9}, {%0,%1,%2,%3};"
        : "+f"(c[0]), "+f"(c[1]), "+f"(c[2]), "+f"(c[3])
        : "r"(a[0]), "r"(a[1]), "r"(a[2]), "r"(a[3]), "r"(b[0]), "r"(b[1]));
}

// Quad layout: 16-row block rb, k-group kk, quad (g,t) at byte
//   rb*2048 + kk*512 + g*64 + ((t^kk)<<4), words [mhi + 2*khi].
// Fill mapping gives conflict-free scalar STS; quad reads are LDS.128.

__global__ __launch_bounds__(256) void gemm_tc(
    const float* __restrict__ A, const float* __restrict__ B,
    const float* __restrict__ bias, float* __restrict__ C,
    int K, int N, int lda, int ldb,
    long long sA, long long sB, long long sC,
    int mode, float scale)
{
    extern __shared__ __align__(128) uint8_t smem[];  // 2 x (A 16KB + B 32KB)
    const uint32_t sb = (uint32_t)__cvta_generic_to_shared(smem);
    const int tid  = threadIdx.x;
    const int warp = tid >> 5;
    const int lane = tid & 31;
    const int l3  = (lane >> 3) & 1, l4 = (lane >> 4) & 1;
    const int kkl = (lane >> 1) & 3, khi = lane & 1;
    const int g   = lane >> 2,       t   = lane & 3;
    const int wm  = warp & 1,        wn  = warp >> 1;
    const int w01 = warp & 3,        w2  = (warp >> 2) & 1;

    const float* Ab = A + sA * blockIdx.z + (long long)blockIdx.y * 128 * lda;
    const float* Bb = B + sB * blockIdx.z + (long long)blockIdx.x * 256 * ldb;

    int so[4];
    #pragma unroll
    for (int e = 0; e < 4; e++) so[e] = (e ^ kkl) << 4;

    int goffA[4], stsA_[4], goffB[8], stsB_[8];
    #pragma unroll
    for (int i = 0; i < 4; i++) {
        int r = l3 | (w01 << 1) | (l4 << 3) | (w2 << 4) | (i << 5);
        goffA[i] = r * lda + kkl * 8 + khi * 4;
        stsA_[i] = (r >> 4) * 2048 + kkl * 512 + (r & 7) * 64 + ((r >> 3) & 1) * 4 + khi * 8;
    }
    #pragma unroll
    for (int i = 0; i < 8; i++) {
        int r = l3 | (w01 << 1) | (l4 << 3) | (w2 << 4) | ((i & 3) << 5) | ((i >> 2) << 7);
        goffB[i] = r * ldb + kkl * 8 + khi * 4;
        stsB_[i] = (r >> 4) * 2048 + kkl * 512 + (r & 7) * 64 + ((r >> 3) & 1) * 4 + khi * 8;
    }

    float acc[4][8][4] = {};
    float4 pa[4], pb[8];
    #pragma unroll
    for (int i = 0; i < 4; i++) pa[i] = *reinterpret_cast<const float4*>(Ab + goffA[i]);
    #pragma unroll
    for (int i = 0; i < 8; i++) pb[i] = *reinterpret_cast<const float4*>(Bb + goffB[i]);

    const int ns = K >> 5;
    for (int s = 0; s < ns; s++) {
        const uint32_t bufA = sb + (s & 1) * 49152;
        const uint32_t bufB = bufA + 16384;
        #pragma unroll
        for (int i = 0; i < 4; i++) {
            uint32_t a_ = bufA + stsA_[i];
            asm volatile("st.shared.b32 [%0], %1;" :: "r"(a_ + so[0]), "r"(__float_as_uint(pa[i].x)) : "memory");
            asm volatile("st.shared.b32 [%0], %1;" :: "r"(a_ + so[1]), "r"(__float_as_uint(pa[i].y)) : "memory");
            asm volatile("st.shared.b32 [%0], %1;" :: "r"(a_ + so[2]), "r"(__float_as_uint(pa[i].z)) : "memory");
            asm volatile("st.shared.b32 [%0], %1;" :: "r"(a_ + so[3]), "r"(__float_as_uint(pa[i].w)) : "memory");
        }
        #pragma unroll
        for (int i = 0; i < 8; i++) {
            uint32_t b_ = bufB + stsB_[i];
            asm volatile("st.shared.b32 [%0], %1;" :: "r"(b_ + so[0]), "r"(__float_as_uint(pb[i].x)) : "memory");
            asm volatile("st.shared.b32 [%0], %1;" :: "r"(b_ + so[1]), "r"(__float_as_uint(pb[i].y)) : "memory");
            asm volatile("st.shared.b32 [%0], %1;" :: "r"(b_ + so[2]), "r"(__float_as_uint(pb[i].z)) : "memory");
            asm volatile("st.shared.b32 [%0], %1;" :: "r"(b_ + so[3]), "r"(__float_as_uint(pb[i].w)) : "memory");
        }
        __syncthreads();

        if (s + 1 < ns) {
            const int k0 = (s + 1) << 5;
            #pragma unroll
            for (int i = 0; i < 4; i++) pa[i] = *reinterpret_cast<const float4*>(Ab + goffA[i] + k0);
            #pragma unroll
            for (int i = 0; i < 8; i++) pb[i] = *reinterpret_cast<const float4*>(Bb + goffB[i] + k0);
        }

        #pragma unroll
        for (int kk = 0; kk < 4; kk++) {
            const uint32_t base = (kk << 9) + (g << 6) + ((t ^ kk) << 4);
            uint32_t bq[4][4];
            #pragma unroll
            for (int p = 0; p < 4; p++) {
                uint4 v;
                asm volatile("ld.shared.v4.b32 {%0,%1,%2,%3}, [%4];"
                             : "=r"(v.x), "=r"(v.y), "=r"(v.z), "=r"(v.w)
                             : "r"(bufB + (((uint32_t)(wn * 4 + p)) << 11) + base));
                bq[p][0] = v.x; bq[p][1] = v.y; bq[p][2] = v.z; bq[p][3] = v.w;
            }
            #pragma unroll
            for (int mt = 0; mt < 4; mt++) {
                uint4 v;
                asm volatile("ld.shared.v4.b32 {%0,%1,%2,%3}, [%4];"
                             : "=r"(v.x), "=r"(v.y), "=r"(v.z), "=r"(v.w)
                             : "r"(bufA + (((uint32_t)(wm * 4 + mt)) << 11) + base));
                uint32_t af[4] = {v.x, v.y, v.z, v.w};
                #pragma unroll
                for (int p = 0; p < 4; p++) {
                    uint32_t b0[2] = {bq[p][0], bq[p][2]};
                    uint32_t b1[2] = {bq[p][1], bq[p][3]};
                    mma_tf32(acc[mt][2 * p    ], af, b0);
                    mma_tf32(acc[mt][2 * p + 1], af, b1);
                }
            }
        }
    }

    // Epilogue
    const int region = (mode == 0) ? (blockIdx.x >> 2) : 0;
    #pragma unroll
    for (int mt = 0; mt < 4; mt++) {
        const int row = blockIdx.y * 128 + wm * 64 + mt * 16 + g;
        #pragma unroll
        for (int nt = 0; nt < 8; nt++) {
            const int col = blockIdx.x * 256 + wn * 64 + nt * 8 + t * 2;
            const float c0 = acc[mt][nt][0], c1 = acc[mt][nt][1];
            const float c2 = acc[mt][nt][2], c3 = acc[mt][nt][3];
            if (mode == 1) {
                float* Cp = C + sC * blockIdx.z;
                float2 lo = {c0 * scale, c1 * scale};
                float2 hi = {c2 * scale, c3 * scale};
                *reinterpret_cast<float2*>(Cp + (long long)row * N + col)       = lo;
                *reinterpret_cast<float2*>(Cp + (long long)(row + 8) * N + col) = hi;
            } else {
                const int bb = row >> 12;
                const int ss = row & 4095;
                const long long base = (long long)bb << 22;
                const float b0 = bias[col], b1 = bias[col + 1];
                if (region == 0) {
                    float2 lo = {rtf((c0 + b0) * 0.03125f), rtf((c1 + b1) * 0.03125f)};
                    float2 hi = {rtf((c2 + b0) * 0.03125f), rtf((c3 + b1) * 0.03125f)};
                    float* dst = g_q + base + (long long)ss * 1024 + col;
                    *reinterpret_cast<float2*>(dst)        = lo;
                    *reinterpret_cast<float2*>(dst + 8192) = hi;   // (ss+8)*1024
                } else if (region == 1) {
                    float2 lo = {rtf(c0 + b0), rtf(c1 + b1)};
                    float2 hi = {rtf(c2 + b0), rtf(c3 + b1)};
                    float* dst = g_k + base + (long long)ss * 1024 + (col - 1024);
                    *reinterpret_cast<float2*>(dst)        = lo;
                    *reinterpret_cast<float2*>(dst + 8192) = hi;
                } else {
                    const int d = col - 2048;
                    float* vt = g_vt + base + ss;
                    vt[(long long)d * 4096]           = rtf(c0 + b0);
                    vt[(long long)(d + 1) * 4096]     = rtf(c1 + b1);
                    vt[(long long)d * 4096 + 8]       = rtf(c2 + b0);
                    vt[(long long)(d + 1) * 4096 + 8] = rtf(c3 + b1);
                }
            }
        }
    }
}

// Round f32 -> tf32(RNA) copy, float4 grid-stride.
__global__ __launch_bounds__(256) void round_copy(float* __restrict__ dst,
                                                  const float* __restrict__ src, int n4)
{
    int i = blockIdx.x * blockDim.x + threadIdx.x;
    if (i < n4) {
        float4 v = reinterpret_cast<const float4*>(src)[i];
        v.x = rtf(v.x); v.y = rtf(v.y); v.z = rtf(v.z); v.w = rtf(v.w);
        reinterpret_cast<float4*>(dst)[i] = v;
    }
}

// One block per row of 4096 floats; in-place softmax, tf32-rounded output.
__global__ __launch_bounds__(256) void softmax_rows(float* __restrict__ S)
{
    float* p = S + (long long)blockIdx.x * 4096;
    const int tid  = threadIdx.x;
    const int warp = tid >> 5;
    const int lane = tid & 31;
    __shared__ float red[8];

    float4 v[4];
    float m = -3.4e38f;
    #pragma unroll
    for (int i = 0; i < 4; i++) {
        v[i] = reinterpret_cast<float4*>(p)[tid + i * 256];
        m = fmaxf(m, fmaxf(fmaxf(v[i].x, v[i].y), fmaxf(v[i].z, v[i].w)));
    }
    #pragma unroll
    for (int o = 16; o > 0; o >>= 1) m = fmaxf(m, __shfl_xor_sync(0xffffffffu, m, o));
    if (lane == 0) red[warp] = m;
    __syncthreads();
    m = red[0];
    #pragma unroll
    for (int i = 1; i < 8; i++) m = fmaxf(m, red[i]);
    __syncthreads();

    float sum = 0.f;
    #pragma unroll
    for (int i = 0; i < 4; i++) {
        v[i].x = __expf(v[i].x - m); v[i].y = __expf(v[i].y - m);
        v[i].z = __expf(v[i].z - m); v[i].w = __expf(v[i].w - m);
        sum += v[i].x + v[i].y + v[i].z + v[i].w;
    }
    #pragma unroll
    for (int o = 16; o > 0; o >>= 1) sum += __shfl_xor_sync(0xffffffffu, sum, o);
    if (lane == 0) red[warp] = sum;
    __syncthreads();
    sum = red[0] + red[1] + red[2] + red[3] + red[4] + red[5] + red[6] + red[7];

    const float inv = 1.0f / sum;
    #pragma unroll
    for (int i = 0; i < 4; i++) {
        v[i].x = rtf(v[i].x * inv); v[i].y = rtf(v[i].y * inv);
        v[i].z = rtf(v[i].z * inv); v[i].w = rtf(v[i].w * inv);
        reinterpret_cast<float4*>(p)[tid + i * 256] = v[i];
    }
}

extern "C" void kernel_launch(void* const* d_in, const int* in_sizes, int n_in,
                              void* d_out, int out_size)
{
    const float* X    = (const float*)d_in[0];
    const float* W    = (const float*)d_in[1];
    const float* bias = (const float*)d_in[2];
    float*       out  = (float*)d_out;

    float *x, *w, *q, *k, *vt, *s;
    cudaGetSymbolAddress((void**)&x,  g_x);
    cudaGetSymbolAddress((void**)&w,  g_w);
    cudaGetSymbolAddress((void**)&q,  g_q);
    cudaGetSymbolAddress((void**)&k,  g_k);
    cudaGetSymbolAddress((void**)&vt, g_vt);
    cudaGetSymbolAddress((void**)&s,  g_s);

    static int once = 0;
    if (!once) {
        cudaFuncSetAttribute(gemm_tc, cudaFuncAttributeMaxDynamicSharedMemorySize, 98304);
        once = 1;
    }

    // 0) pre-round X, W to tf32 (RNA)
    round_copy<<<16384, 256>>>(x, X, 16777216 / 4);
    round_copy<<< 3072, 256>>>(w, W,  3145728 / 4);

    // 1) QKV projection: [16384,1024] @ [3072,1024]^T -> route Q/32, K, Vt
    gemm_tc<<<dim3(12, 128, 1), 256, 98304>>>(x, w, bias, nullptr,
                                              1024, 3072, 1024, 1024,
                                              0, 0, 0, /*mode=*/0, 1.0f);
    // 2) Scores: per-batch [4096,1024] @ [4096,1024]^T
    gemm_tc<<<dim3(16, 32, 4), 256, 98304>>>(q, k, bias, s,
                                             1024, 4096, 1024, 1024,
                                             1LL << 22, 1LL << 22, 1LL << 24,
                                             /*mode=*/1, 1.0f);
    // 3) Row softmax (rounds output)
    softmax_rows<<<16384, 256>>>(s);
    // 4) Output: per-batch [4096,4096] @ [1024,4096]^T
    gemm_tc<<<dim3(4, 32, 4), 256, 98304>>>(s, vt, bias, out,
                                            4096, 1024, 4096, 4096,
                                            1LL << 24, 1LL << 22, 1LL << 22,
                                            /*mode=*/1, 1.0f);
}

// round 5
// speedup vs baseline: 2.4570x; 1.2422x over previous
#include <cuda_runtime.h>
#include <cstdint>

// ---------------------------------------------------------------------------
// SelfAttentionV2, round 5: cp.async (LDGSTS) 3-stage pipeline + ldmatrix
// fragment loads + mma.sync tf32. CTA 128x256x32, warp tile 64x64.
// Operands pre-rounded to tf32 in gmem (no cvt, no STS in mainloop).
// ---------------------------------------------------------------------------

__device__ float g_x [16777216];   // rounded X
__device__ float g_w [ 3145728];   // rounded W
__device__ float g_q [16777216];   // rounded, pre-scaled 1/32
__device__ float g_k [16777216];   // rounded
__device__ float g_vt[16777216];   // rounded, [b][d][s]
__device__ float g_s [67108864];   // scores [b][q][k]; rounded after softmax

__device__ __forceinline__ uint32_t f2tf(float f) {
    uint32_t u;
    asm("cvt.rna.tf32.f32 %0, %1;" : "=r"(u) : "f"(f));
    return u;
}
__device__ __forceinline__ float rtf(float f) { return __uint_as_float(f2tf(f)); }

__device__ __forceinline__ void mma_tf32(float c[4], const uint32_t a[4], const uint32_t b[2]) {
    asm volatile(
        "mma.sync.aligned.m16n8k8.row.col.f32.tf32.tf32.f32 "
        "{%0,%1,%2,%3}, {%4,%5,%6,%7}, {%8,%9}, {%0,%1,%2,%3};"
        : "+f"(c[0]), "+f"(c[1]), "+f"(c[2]), "+f"(c[3])
        : "r"(a[0]), "r"(a[1]), "r"(a[2]), "r"(a[3]), "r"(b[0]), "r"(b[1]));
}

#define LDSM4(v, addr)                                                     \
    asm volatile("ldmatrix.sync.aligned.m8n8.x4.shared.b16 {%0,%1,%2,%3}, [%4];" \
                 : "=r"((v).x), "=r"((v).y), "=r"((v).z), "=r"((v).w) : "r"(addr))

#define CPA16(sm, gm)                                                      \
    asm volatile("cp.async.cg.shared.global [%0], [%1], 16;"               \
                 :: "r"(sm), "l"(gm) : "memory")

// Tiles in smem: row-major, 128 B per row (32 tf32), SW128 swizzle:
// chunk(r, j) at byte (r*128 + j*16) ^ ((r&7)<<4). Stage = A 16KB + B 32KB.

__global__ __launch_bounds__(256, 1) void gemm_tc(
    const float* __restrict__ A, const float* __restrict__ B,
    const float* __restrict__ bias, float* __restrict__ C,
    int K, int N, int lda, int ldb,
    long long sA, long long sB, long long sC,
    int mode, float scale)
{
    extern __shared__ __align__(1024) uint8_t smem[];   // 3 x 48KB
    const uint32_t sb = (uint32_t)__cvta_generic_to_shared(smem);
    const int tid  = threadIdx.x;
    const int warp = tid >> 5;
    const int lane = tid & 31;
    const int wm = warp & 1, wn = warp >> 1;

    // ldmatrix lane roles
    const int rlA = lane & 15, khalf = lane >> 4;          // A: rows, k-half
    const uint32_t xorA  = (uint32_t)(rlA & 7) << 4;
    const uint32_t aBase = (uint32_t)(wm * 64 + rlA) * 128;
    const uint32_t kselA = (uint32_t)khalf << 4;
    const int mB = lane >> 3, rjB = lane & 7;              // B: 4 matrices
    const uint32_t xorB  = (uint32_t)rjB << 4;
    const uint32_t bBase = (uint32_t)(wn * 64 + ((mB >> 1) << 3) + rjB) * 128;
    const uint32_t kselB = (uint32_t)(mB & 1) << 4;

    const float* Ab = A + sA * blockIdx.z + (long long)blockIdx.y * 128 * lda;
    const float* Bb = B + sB * blockIdx.z + (long long)blockIdx.x * 256 * ldb;

    float acc[4][8][4] = {};
    const int ns = K >> 5;

    // --- async fill of one k-slice into stage buffer ---
    #define ISSUE(S)                                                          \
    do {                                                                      \
        const uint32_t ba = sb + ((S) % 3) * 49152;                           \
        const int k0 = (S) << 5;                                              \
        _Pragma("unroll")                                                     \
        for (int i = 0; i < 4; i++) {                                         \
            int id = tid + i * 256, r = id >> 3, j = id & 7;                  \
            uint32_t so = ((uint32_t)(r * 128 + j * 16)) ^ ((uint32_t)(r & 7) << 4); \
            CPA16(ba + so, Ab + (long long)r * lda + k0 + j * 4);             \
        }                                                                     \
        _Pragma("unroll")                                                     \
        for (int i = 0; i < 8; i++) {                                         \
            int id = tid + i * 256, r = id >> 3, j = id & 7;                  \
            uint32_t so = ((uint32_t)(r * 128 + j * 16)) ^ ((uint32_t)(r & 7) << 4); \
            CPA16(ba + 16384 + so, Bb + (long long)r * ldb + k0 + j * 4);     \
        }                                                                     \
        asm volatile("cp.async.commit_group;" ::: "memory");                  \
    } while (0)

    ISSUE(0);
    ISSUE(1);

    for (int s = 0; s < ns; s++) {
        if (s + 1 < ns) asm volatile("cp.async.wait_group 1;" ::: "memory");
        else            asm volatile("cp.async.wait_group 0;" ::: "memory");
        __syncthreads();
        if (s + 2 < ns) ISSUE(s + 2);

        const uint32_t bufA = sb + (s % 3) * 49152;
        const uint32_t bufB = bufA + 16384;
        #pragma unroll
        for (int kk = 0; kk < 4; kk++) {
            const uint32_t aoff = (((uint32_t)kk << 5) + kselA) ^ xorA;
            const uint32_t boff = (((uint32_t)kk << 5) + kselB) ^ xorB;
            uint32_t bq[4][4];
            #pragma unroll
            for (int p = 0; p < 4; p++) {
                uint4 v;
                LDSM4(v, bufB + bBase + p * 2048 + boff);
                bq[p][0] = v.x; bq[p][1] = v.y; bq[p][2] = v.z; bq[p][3] = v.w;
            }
            #pragma unroll
            for (int mt = 0; mt < 4; mt++) {
                uint4 v;
                LDSM4(v, bufA + aBase + mt * 2048 + aoff);
                uint32_t af[4] = {v.x, v.y, v.z, v.w};
                #pragma unroll
                for (int p = 0; p < 4; p++) {
                    uint32_t b0[2] = {bq[p][0], bq[p][1]};   // n-tile 2p
                    uint32_t b1[2] = {bq[p][2], bq[p][3]};   // n-tile 2p+1
                    mma_tf32(acc[mt][2 * p    ], af, b0);
                    mma_tf32(acc[mt][2 * p + 1], af, b1);
                }
            }
        }
    }

    // Epilogue (thread fragment: rows g,g+8; cols t*2, t*2+1)
    const int g = lane >> 2, t = lane & 3;
    const int region = (mode == 0) ? (blockIdx.x >> 2) : 0;
    #pragma unroll
    for (int mt = 0; mt < 4; mt++) {
        const int row = blockIdx.y * 128 + wm * 64 + mt * 16 + g;
        #pragma unroll
        for (int nt = 0; nt < 8; nt++) {
            const int col = blockIdx.x * 256 + wn * 64 + nt * 8 + t * 2;
            const float c0 = acc[mt][nt][0], c1 = acc[mt][nt][1];
            const float c2 = acc[mt][nt][2], c3 = acc[mt][nt][3];
            if (mode == 1) {
                float* Cp = C + sC * blockIdx.z;
                float2 lo = {c0 * scale, c1 * scale};
                float2 hi = {c2 * scale, c3 * scale};
                *reinterpret_cast<float2*>(Cp + (long long)row * N + col)       = lo;
                *reinterpret_cast<float2*>(Cp + (long long)(row + 8) * N + col) = hi;
            } else {
                const int bb = row >> 12;
                const int ss = row & 4095;
                const long long base = (long long)bb << 22;
                const float b0 = bias[col], b1 = bias[col + 1];
                if (region == 0) {
                    float2 lo = {rtf((c0 + b0) * 0.03125f), rtf((c1 + b1) * 0.03125f)};
                    float2 hi = {rtf((c2 + b0) * 0.03125f), rtf((c3 + b1) * 0.03125f)};
                    float* dst = g_q + base + (long long)ss * 1024 + col;
                    *reinterpret_cast<float2*>(dst)        = lo;
                    *reinterpret_cast<float2*>(dst + 8192) = hi;
                } else if (region == 1) {
                    float2 lo = {rtf(c0 + b0), rtf(c1 + b1)};
                    float2 hi = {rtf(c2 + b0), rtf(c3 + b1)};
                    float* dst = g_k + base + (long long)ss * 1024 + (col - 1024);
                    *reinterpret_cast<float2*>(dst)        = lo;
                    *reinterpret_cast<float2*>(dst + 8192) = hi;
                } else {
                    const int d = col - 2048;
                    float* vt = g_vt + base + ss;
                    vt[(long long)d * 4096]           = rtf(c0 + b0);
                    vt[(long long)(d + 1) * 4096]     = rtf(c1 + b1);
                    vt[(long long)d * 4096 + 8]       = rtf(c2 + b0);
                    vt[(long long)(d + 1) * 4096 + 8] = rtf(c3 + b1);
                }
            }
        }
    }
}

// Round f32 -> tf32(RNA) copy, float4.
__global__ __launch_bounds__(256) void round_copy(float* __restrict__ dst,
                                                  const float* __restrict__ src, int n4)
{
    int i = blockIdx.x * blockDim.x + threadIdx.x;
    if (i < n4) {
        float4 v = reinterpret_cast<const float4*>(src)[i];
        v.x = rtf(v.x); v.y = rtf(v.y); v.z = rtf(v.z); v.w = rtf(v.w);
        reinterpret_cast<float4*>(dst)[i] = v;
    }
}

// One block per row of 4096 floats; in-place softmax, tf32-rounded output.
__global__ __launch_bounds__(256) void softmax_rows(float* __restrict__ S)
{
    float* p = S + (long long)blockIdx.x * 4096;
    const int tid  = threadIdx.x;
    const int warp = tid >> 5;
    const int lane = tid & 31;
    __shared__ float red[8];

    float4 v[4];
    float m = -3.4e38f;
    #pragma unroll
    for (int i = 0; i < 4; i++) {
        v[i] = reinterpret_cast<float4*>(p)[tid + i * 256];
        m = fmaxf(m, fmaxf(fmaxf(v[i].x, v[i].y), fmaxf(v[i].z, v[i].w)));
    }
    #pragma unroll
    for (int o = 16; o > 0; o >>= 1) m = fmaxf(m, __shfl_xor_sync(0xffffffffu, m, o));
    if (lane == 0) red[warp] = m;
    __syncthreads();
    m = red[0];
    #pragma unroll
    for (int i = 1; i < 8; i++) m = fmaxf(m, red[i]);
    __syncthreads();

    float sum = 0.f;
    #pragma unroll
    for (int i = 0; i < 4; i++) {
        v[i].x = __expf(v[i].x - m); v[i].y = __expf(v[i].y - m);
        v[i].z = __expf(v[i].z - m); v[i].w = __expf(v[i].w - m);
        sum += v[i].x + v[i].y + v[i].z + v[i].w;
    }
    #pragma unroll
    for (int o = 16; o > 0; o >>= 1) sum += __shfl_xor_sync(0xffffffffu, sum, o);
    if (lane == 0) red[warp] = sum;
    __syncthreads();
    sum = red[0] + red[1] + red[2] + red[3] + red[4] + red[5] + red[6] + red[7];

    const float inv = 1.0f / sum;
    #pragma unroll
    for (int i = 0; i < 4; i++) {
        v[i].x = rtf(v[i].x * inv); v[i].y = rtf(v[i].y * inv);
        v[i].z = rtf(v[i].z * inv); v[i].w = rtf(v[i].w * inv);
        reinterpret_cast<float4*>(p)[tid + i * 256] = v[i];
    }
}

extern "C" void kernel_launch(void* const* d_in, const int* in_sizes, int n_in,
                              void* d_out, int out_size)
{
    const float* X    = (const float*)d_in[0];
    const float* W    = (const float*)d_in[1];
    const float* bias = (const float*)d_in[2];
    float*       out  = (float*)d_out;

    float *x, *w, *q, *k, *vt, *s;
    cudaGetSymbolAddress((void**)&x,  g_x);
    cudaGetSymbolAddress((void**)&w,  g_w);
    cudaGetSymbolAddress((void**)&q,  g_q);
    cudaGetSymbolAddress((void**)&k,  g_k);
    cudaGetSymbolAddress((void**)&vt, g_vt);
    cudaGetSymbolAddress((void**)&s,  g_s);

    static int once = 0;
    if (!once) {
        cudaFuncSetAttribute(gemm_tc, cudaFuncAttributeMaxDynamicSharedMemorySize, 147456);
        once = 1;
    }

    // 0) pre-round X, W to tf32 (RNA)
    round_copy<<<16384, 256>>>(x, X, 16777216 / 4);
    round_copy<<< 3072, 256>>>(w, W,  3145728 / 4);

    // 1) QKV projection -> route Q/32, K, Vt
    gemm_tc<<<dim3(12, 128, 1), 256, 147456>>>(x, w, bias, nullptr,
                                               1024, 3072, 1024, 1024,
                                               0, 0, 0, /*mode=*/0, 1.0f);
    // 2) Scores: per-batch [4096,1024] @ [4096,1024]^T
    gemm_tc<<<dim3(16, 32, 4), 256, 147456>>>(q, k, bias, s,
                                              1024, 4096, 1024, 1024,
                                              1LL << 22, 1LL << 22, 1LL << 24,
                                              /*mode=*/1, 1.0f);
    // 3) Row softmax (rounds output)
    softmax_rows<<<16384, 256>>>(s);
    // 4) Output: per-batch [4096,4096] @ [1024,4096]^T
    gemm_tc<<<dim3(4, 32, 4), 256, 147456>>>(s, vt, bias, out,
                                             4096, 1024, 4096, 4096,
                                             1LL << 24, 1LL << 22, 1LL << 22,
                                             /*mode=*/1, 1.0f);
}

// round 6
// speedup vs baseline: 2.6818x; 1.0915x over previous
#include <cuda_runtime.h>
#include <cstdint>

// ---------------------------------------------------------------------------
// SelfAttentionV2, round 6: cp.async 2-stage pipeline with K-slice 64
// (2 x 48KB sub-tiles per stage, 192KB smem), ldmatrix + mma.sync tf32,
// CTA 128x256, warp tile 64x64. Split-K=2 for the PV GEMM + reduce pass.
// ---------------------------------------------------------------------------

__device__ float g_x [16777216];   // rounded X
__device__ float g_w [ 3145728];   // rounded W
__device__ float g_q [16777216];   // rounded, pre-scaled 1/32
__device__ float g_k [16777216];   // rounded
__device__ float g_vt[16777216];   // rounded, [b][d][s]
__device__ float g_s [67108864];   // scores [b][q][k]; rounded after softmax
__device__ float g_p [33554432];   // PV split-K partials (2 x 64MB)

__device__ __forceinline__ uint32_t f2tf(float f) {
    uint32_t u;
    asm("cvt.rna.tf32.f32 %0, %1;" : "=r"(u) : "f"(f));
    return u;
}
__device__ __forceinline__ float rtf(float f) { return __uint_as_float(f2tf(f)); }

__device__ __forceinline__ void mma_tf32(float c[4], const uint32_t a[4], const uint32_t b[2]) {
    asm volatile(
        "mma.sync.aligned.m16n8k8.row.col.f32.tf32.tf32.f32 "
        "{%0,%1,%2,%3}, {%4,%5,%6,%7}, {%8,%9}, {%0,%1,%2,%3};"
        : "+f"(c[0]), "+f"(c[1]), "+f"(c[2]), "+f"(c[3])
        : "r"(a[0]), "r"(a[1]), "r"(a[2]), "r"(a[3]), "r"(b[0]), "r"(b[1]));
}

#define LDSM4(v, addr)                                                     \
    asm volatile("ldmatrix.sync.aligned.m8n8.x4.shared.b16 {%0,%1,%2,%3}, [%4];" \
                 : "=r"((v).x), "=r"((v).y), "=r"((v).z), "=r"((v).w) : "r"(addr))

#define CPA16(sm, gm)                                                      \
    asm volatile("cp.async.cg.shared.global [%0], [%1], 16;"               \
                 :: "r"(sm), "l"(gm) : "memory")

// Stage layout (96KB): A0[0,16K) A1[16K,32K) B0[32K,64K) B1[64K,96K).
// Sub-tiles are k=32 slices, row-major 128B rows, SW128 swizzle:
// chunk(r,jj) at byte (r*128 + jj*16) ^ ((r&7)<<4).

__global__ __launch_bounds__(256, 1) void gemm_tc(
    const float* __restrict__ A, const float* __restrict__ B,
    const float* __restrict__ bias, float* __restrict__ C,
    int K, int N, int lda, int ldb,
    long long sA, long long sB, long long sC,
    int zshift, long long koffA, long long koffB, long long koffC,
    int mode, float scale)
{
    extern __shared__ __align__(1024) uint8_t smem[];   // 2 x 96KB
    const uint32_t sb = (uint32_t)__cvta_generic_to_shared(smem);
    const int tid  = threadIdx.x;
    const int warp = tid >> 5;
    const int lane = tid & 31;
    const int wm = warp & 1, wn = warp >> 1;

    const int zb = blockIdx.z & ((1 << zshift) - 1);   // batch
    const int zt = blockIdx.z >> zshift;               // k-split index

    // ldmatrix lane roles
    const int rlA = lane & 15, khalf = lane >> 4;
    const uint32_t xorA  = (uint32_t)(rlA & 7) << 4;
    const uint32_t aBase = (uint32_t)(wm * 64 + rlA) * 128;
    const uint32_t kselA = (uint32_t)khalf << 4;
    const int mB = lane >> 3, rjB = lane & 7;
    const uint32_t xorB  = (uint32_t)rjB << 4;
    const uint32_t bBase = (uint32_t)(wn * 64 + ((mB >> 1) << 3) + rjB) * 128;
    const uint32_t kselB = (uint32_t)(mB & 1) << 4;

    const float* Ab = A + sA * zb + koffA * zt + (long long)blockIdx.y * 128 * lda;
    const float* Bb = B + sB * zb + koffB * zt + (long long)blockIdx.x * 256 * ldb;

    float acc[4][8][4] = {};
    const int ns = K >> 6;

    #define ISSUE(S)                                                          \
    do {                                                                      \
        const uint32_t ba = sb + ((S) & 1) * 98304;                           \
        const int k0 = (S) << 6;                                              \
        _Pragma("unroll")                                                     \
        for (int i = 0; i < 8; i++) {                                         \
            int id = tid + i * 256, r = id >> 4, j = id & 15;                 \
            int h = j >> 3, jj = j & 7;                                       \
            uint32_t so = ((uint32_t)(r * 128 + jj * 16)) ^ ((uint32_t)(r & 7) << 4); \
            CPA16(ba + h * 16384 + so, Ab + (long long)r * lda + k0 + h * 32 + jj * 4); \
        }                                                                     \
        _Pragma("unroll")                                                     \
        for (int i = 0; i < 16; i++) {                                        \
            int id = tid + i * 256, r = id >> 4, j = id & 15;                 \
            int h = j >> 3, jj = j & 7;                                       \
            uint32_t so = ((uint32_t)(r * 128 + jj * 16)) ^ ((uint32_t)(r & 7) << 4); \
            CPA16(ba + 32768 + h * 32768 + so, Bb + (long long)r * ldb + k0 + h * 32 + jj * 4); \
        }                                                                     \
        asm volatile("cp.async.commit_group;" ::: "memory");                  \
    } while (0)

    ISSUE(0);
    if (ns > 1) ISSUE(1);

    for (int s = 0; s < ns; s++) {
        if (s + 1 < ns) asm volatile("cp.async.wait_group 1;" ::: "memory");
        else            asm volatile("cp.async.wait_group 0;" ::: "memory");
        __syncthreads();

        const uint32_t stage = sb + (s & 1) * 98304;
        #pragma unroll
        for (int h = 0; h < 2; h++) {
            const uint32_t bufA = stage + h * 16384;
            const uint32_t bufB = stage + 32768 + h * 32768;
            #pragma unroll
            for (int kk = 0; kk < 4; kk++) {
                const uint32_t aoff = (((uint32_t)kk << 5) + kselA) ^ xorA;
                const uint32_t boff = (((uint32_t)kk << 5) + kselB) ^ xorB;
                uint32_t bq[4][4];
                #pragma unroll
                for (int p = 0; p < 4; p++) {
                    uint4 v;
                    LDSM4(v, bufB + bBase + p * 2048 + boff);
                    bq[p][0] = v.x; bq[p][1] = v.y; bq[p][2] = v.z; bq[p][3] = v.w;
                }
                #pragma unroll
                for (int mt = 0; mt < 4; mt++) {
                    uint4 v;
                    LDSM4(v, bufA + aBase + mt * 2048 + aoff);
                    uint32_t af[4] = {v.x, v.y, v.z, v.w};
                    #pragma unroll
                    for (int p = 0; p < 4; p++) {
                        uint32_t b0[2] = {bq[p][0], bq[p][1]};
                        uint32_t b1[2] = {bq[p][2], bq[p][3]};
                        mma_tf32(acc[mt][2 * p    ], af, b0);
                        mma_tf32(acc[mt][2 * p + 1], af, b1);
                    }
                }
            }
        }
        __syncthreads();
        if (s + 2 < ns) ISSUE(s + 2);
    }

    // Epilogue (thread fragment: rows g,g+8; cols t*2,t*2+1)
    const int g = lane >> 2, t = lane & 3;
    const int region = (mode == 0) ? (blockIdx.x >> 2) : 0;
    #pragma unroll
    for (int mt = 0; mt < 4; mt++) {
        const int row = blockIdx.y * 128 + wm * 64 + mt * 16 + g;
        #pragma unroll
        for (int nt = 0; nt < 8; nt++) {
            const int col = blockIdx.x * 256 + wn * 64 + nt * 8 + t * 2;
            const float c0 = acc[mt][nt][0], c1 = acc[mt][nt][1];
            const float c2 = acc[mt][nt][2], c3 = acc[mt][nt][3];
            if (mode == 1) {
                float* Cp = C + sC * zb + koffC * zt;
                float2 lo = {c0 * scale, c1 * scale};
                float2 hi = {c2 * scale, c3 * scale};
                *reinterpret_cast<float2*>(Cp + (long long)row * N + col)       = lo;
                *reinterpret_cast<float2*>(Cp + (long long)(row + 8) * N + col) = hi;
            } else {
                const int bb = row >> 12;
                const int ss = row & 4095;
                const long long base = (long long)bb << 22;
                const float b0 = bias[col], b1 = bias[col + 1];
                if (region == 0) {
                    float2 lo = {rtf((c0 + b0) * 0.03125f), rtf((c1 + b1) * 0.03125f)};
                    float2 hi = {rtf((c2 + b0) * 0.03125f), rtf((c3 + b1) * 0.03125f)};
                    float* dst = g_q + base + (long long)ss * 1024 + col;
                    *reinterpret_cast<float2*>(dst)        = lo;
                    *reinterpret_cast<float2*>(dst + 8192) = hi;
                } else if (region == 1) {
                    float2 lo = {rtf(c0 + b0), rtf(c1 + b1)};
                    float2 hi = {rtf(c2 + b0), rtf(c3 + b1)};
                    float* dst = g_k + base + (long long)ss * 1024 + (col - 1024);
                    *reinterpret_cast<float2*>(dst)        = lo;
                    *reinterpret_cast<float2*>(dst + 8192) = hi;
                } else {
                    const int d = col - 2048;
                    float* vt = g_vt + base + ss;
                    vt[(long long)d * 4096]           = rtf(c0 + b0);
                    vt[(long long)(d + 1) * 4096]     = rtf(c1 + b1);
                    vt[(long long)d * 4096 + 8]       = rtf(c2 + b0);
                    vt[(long long)(d + 1) * 4096 + 8] = rtf(c3 + b1);
                }
            }
        }
    }
}

// out = p0 + p1 (split-K reduction), float4.
__global__ __launch_bounds__(256) void reduce_add(float* __restrict__ out,
                                                  const float* __restrict__ p, int n4)
{
    int i = blockIdx.x * blockDim.x + threadIdx.x;
    if (i < n4) {
        float4 a = reinterpret_cast<const float4*>(p)[i];
        float4 b = reinterpret_cast<const float4*>(p + 16777216)[i];
        float4 o = {a.x + b.x, a.y + b.y, a.z + b.z, a.w + b.w};
        reinterpret_cast<float4*>(out)[i] = o;
    }
}

// Round f32 -> tf32(RNA) copy, float4.
__global__ __launch_bounds__(256) void round_copy(float* __restrict__ dst,
                                                  const float* __restrict__ src, int n4)
{
    int i = blockIdx.x * blockDim.x + threadIdx.x;
    if (i < n4) {
        float4 v = reinterpret_cast<const float4*>(src)[i];
        v.x = rtf(v.x); v.y = rtf(v.y); v.z = rtf(v.z); v.w = rtf(v.w);
        reinterpret_cast<float4*>(dst)[i] = v;
    }
}

// One block per row of 4096 floats; in-place softmax, tf32-rounded output.
__global__ __launch_bounds__(256) void softmax_rows(float* __restrict__ S)
{
    float* p = S + (long long)blockIdx.x * 4096;
    const int tid  = threadIdx.x;
    const int warp = tid >> 5;
    const int lane = tid & 31;
    __shared__ float red[8];

    float4 v[4];
    float m = -3.4e38f;
    #pragma unroll
    for (int i = 0; i < 4; i++) {
        v[i] = reinterpret_cast<float4*>(p)[tid + i * 256];
        m = fmaxf(m, fmaxf(fmaxf(v[i].x, v[i].y), fmaxf(v[i].z, v[i].w)));
    }
    #pragma unroll
    for (int o = 16; o > 0; o >>= 1) m = fmaxf(m, __shfl_xor_sync(0xffffffffu, m, o));
    if (lane == 0) red[warp] = m;
    __syncthreads();
    m = red[0];
    #pragma unroll
    for (int i = 1; i < 8; i++) m = fmaxf(m, red[i]);
    __syncthreads();

    float sum = 0.f;
    #pragma unroll
    for (int i = 0; i < 4; i++) {
        v[i].x = __expf(v[i].x - m); v[i].y = __expf(v[i].y - m);
        v[i].z = __expf(v[i].z - m); v[i].w = __expf(v[i].w - m);
        sum += v[i].x + v[i].y + v[i].z + v[i].w;
    }
    #pragma unroll
    for (int o = 16; o > 0; o >>= 1) sum += __shfl_xor_sync(0xffffffffu, sum, o);
    if (lane == 0) red[warp] = sum;
    __syncthreads();
    sum = red[0] + red[1] + red[2] + red[3] + red[4] + red[5] + red[6] + red[7];

    const float inv = 1.0f / sum;
    #pragma unroll
    for (int i = 0; i < 4; i++) {
        v[i].x = rtf(v[i].x * inv); v[i].y = rtf(v[i].y * inv);
        v[i].z = rtf(v[i].z * inv); v[i].w = rtf(v[i].w * inv);
        reinterpret_cast<float4*>(p)[tid + i * 256] = v[i];
    }
}

extern "C" void kernel_launch(void* const* d_in, const int* in_sizes, int n_in,
                              void* d_out, int out_size)
{
    const float* X    = (const float*)d_in[0];
    const float* W    = (const float*)d_in[1];
    const float* bias = (const float*)d_in[2];
    float*       out  = (float*)d_out;

    float *x, *w, *q, *k, *vt, *s, *p;
    cudaGetSymbolAddress((void**)&x,  g_x);
    cudaGetSymbolAddress((void**)&w,  g_w);
    cudaGetSymbolAddress((void**)&q,  g_q);
    cudaGetSymbolAddress((void**)&k,  g_k);
    cudaGetSymbolAddress((void**)&vt, g_vt);
    cudaGetSymbolAddress((void**)&s,  g_s);
    cudaGetSymbolAddress((void**)&p,  g_p);

    static int once = 0;
    if (!once) {
        cudaFuncSetAttribute(gemm_tc, cudaFuncAttributeMaxDynamicSharedMemorySize, 196608);
        once = 1;
    }

    // 0) pre-round X, W to tf32 (RNA)
    round_copy<<<16384, 256>>>(x, X, 16777216 / 4);
    round_copy<<< 3072, 256>>>(w, W,  3145728 / 4);

    // 1) QKV projection -> route Q/32, K, Vt
    gemm_tc<<<dim3(12, 128, 1), 256, 196608>>>(x, w, bias, nullptr,
                                               1024, 3072, 1024, 1024,
                                               0, 0, 0,
                                               0, 0, 0, 0,
                                               /*mode=*/0, 1.0f);
    // 2) Scores: per-batch [4096,1024] @ [4096,1024]^T
    gemm_tc<<<dim3(16, 32, 4), 256, 196608>>>(q, k, bias, s,
                                              1024, 4096, 1024, 1024,
                                              1LL << 22, 1LL << 22, 1LL << 24,
                                              2, 0, 0, 0,
                                              /*mode=*/1, 1.0f);
    // 3) Row softmax (rounds output)
    softmax_rows<<<16384, 256>>>(s);
    // 4) Output partials: split-K=2, z = (t<<2)|batch
    gemm_tc<<<dim3(4, 32, 8), 256, 196608>>>(s, vt, bias, p,
                                             2048, 1024, 4096, 4096,
                                             1LL << 24, 1LL << 22, 1LL << 22,
                                             2, 2048, 2048, 16777216LL,
                                             /*mode=*/1, 1.0f);
    // 5) Reduce partials into final output
    reduce_add<<<16384, 256>>>(out, p, 16777216 / 4);
}

// round 7
// speedup vs baseline: 4.6246x; 1.7244x over previous
#include <cuda_runtime.h>
#include <cuda_fp16.h>
#include <cstdint>

// ---------------------------------------------------------------------------
// SelfAttentionV2, round 7: fp16 mma.sync m16n8k16 (2x tf32 throughput,
// same 11-bit significand). cp.async 4-stage pipeline (k-slice 64, 48KB/stage,
// one barrier per slice), ldmatrix x4 fragments. CTA 128x256, warp 64x64.
// Scores kept fp32; probs/V/Q/K/X/W in fp16. Split-K=2 PV + reduce.
// ---------------------------------------------------------------------------

__device__ __half g_x [16777216];   // X  fp16
__device__ __half g_w [ 3145728];   // W  fp16
__device__ __half g_q [16777216];   // Q  fp16, pre-scaled 1/32
__device__ __half g_k [16777216];   // K  fp16
__device__ __half g_vt[16777216];   // V^T fp16 [b][d][s]
__device__ float  g_s [67108864];   // scores fp32 [b][q][k]
__device__ __half g_p [67108864];   // softmax probs fp16 [b][q][k]
__device__ float  g_pt[33554432];   // PV split-K partials (2 x 64MB)

__device__ __forceinline__ void mma_f16(float c[4], const uint32_t a[4], const uint32_t b[2]) {
    asm volatile(
        "mma.sync.aligned.m16n8k16.row.col.f32.f16.f16.f32 "
        "{%0,%1,%2,%3}, {%4,%5,%6,%7}, {%8,%9}, {%0,%1,%2,%3};"
        : "+f"(c[0]), "+f"(c[1]), "+f"(c[2]), "+f"(c[3])
        : "r"(a[0]), "r"(a[1]), "r"(a[2]), "r"(a[3]), "r"(b[0]), "r"(b[1]));
}

#define LDSM4(v, addr)                                                     \
    asm volatile("ldmatrix.sync.aligned.m8n8.x4.shared.b16 {%0,%1,%2,%3}, [%4];" \
                 : "=r"((v).x), "=r"((v).y), "=r"((v).z), "=r"((v).w) : "r"(addr))

#define CPA16(sm, gm)                                                      \
    asm volatile("cp.async.cg.shared.global [%0], [%1], 16;"               \
                 :: "r"(sm), "l"(gm) : "memory")

// Smem tiles: K-major fp16 rows of 64 halves = 128B, SW128 swizzle:
// chunk(r, j) at byte (r*128 + j*16) ^ ((r&7)<<4).
// Stage (48KB): A[0,16K) = 128 rows, B[16K,48K) = 256 rows. 4 stages.

__global__ __launch_bounds__(256, 1) void gemm_tc(
    const __half* __restrict__ A, const __half* __restrict__ B,
    const float* __restrict__ bias, float* __restrict__ C,
    int K, int N, int lda, int ldb,
    long long sA, long long sB, long long sC,
    int zshift, long long koffA, long long koffB, long long koffC,
    int mode, float scale)
{
    extern __shared__ __align__(1024) uint8_t smem[];   // 4 x 48KB
    const uint32_t sb = (uint32_t)__cvta_generic_to_shared(smem);
    const int tid  = threadIdx.x;
    const int warp = tid >> 5;
    const int lane = tid & 31;
    const int wm = warp & 1, wn = warp >> 1;

    const int zb = blockIdx.z & ((1 << zshift) - 1);   // batch
    const int zt = blockIdx.z >> zshift;               // k-split index

    // ldmatrix lane roles (bytes)
    const uint32_t xorr  = (uint32_t)(lane & 7) << 4;
    const uint32_t aBase = (uint32_t)(wm * 64 + (lane & 15)) * 128;
    const uint32_t kselA = (uint32_t)(lane >> 4) << 4;
    const uint32_t bBase = (uint32_t)(wn * 64 + ((lane >> 4) << 3) + (lane & 7)) * 128;
    const uint32_t kselB = (uint32_t)((lane >> 3) & 1) << 4;

    const __half* Ab = A + sA * zb + koffA * zt + (long long)blockIdx.y * 128 * lda;
    const __half* Bb = B + sB * zb + koffB * zt + (long long)blockIdx.x * 256 * ldb;

    float acc[4][8][4] = {};
    const int ns = K >> 6;     // 64 halves per slice

    #define ISSUE(S)                                                          \
    do {                                                                      \
        const uint32_t ba = sb + ((S) & 3) * 49152;                           \
        const int k0 = (S) << 6;                                              \
        _Pragma("unroll")                                                     \
        for (int i = 0; i < 4; i++) {                                         \
            int id = tid + i * 256, r = id >> 3, j = id & 7;                  \
            uint32_t so = ((uint32_t)(r * 128 + j * 16)) ^ ((uint32_t)(r & 7) << 4); \
            CPA16(ba + so, Ab + (long long)r * lda + k0 + j * 8);             \
        }                                                                     \
        _Pragma("unroll")                                                     \
        for (int i = 0; i < 8; i++) {                                         \
            int id = tid + i * 256, r = id >> 3, j = id & 7;                  \
            uint32_t so = ((uint32_t)(r * 128 + j * 16)) ^ ((uint32_t)(r & 7) << 4); \
            CPA16(ba + 16384 + so, Bb + (long long)r * ldb + k0 + j * 8);     \
        }                                                                     \
        asm volatile("cp.async.commit_group;" ::: "memory");                  \
    } while (0)

    ISSUE(0); ISSUE(1); ISSUE(2);

    for (int s = 0; s < ns; s++) {
        if (s + 3 <= ns)      asm volatile("cp.async.wait_group 2;" ::: "memory");
        else if (s + 2 == ns) asm volatile("cp.async.wait_group 1;" ::: "memory");
        else                  asm volatile("cp.async.wait_group 0;" ::: "memory");
        __syncthreads();
        if (s + 3 < ns) ISSUE(s + 3);   // writes buf (s-1)&3: retired last barrier

        const uint32_t bufA = sb + (s & 3) * 49152;
        const uint32_t bufB = bufA + 16384;
        #pragma unroll
        for (int kk = 0; kk < 4; kk++) {                 // K=16 halves per kk
            const uint32_t acol = (((uint32_t)kk << 5) + kselA) ^ xorr;
            const uint32_t bcol = (((uint32_t)kk << 5) + kselB) ^ xorr;
            uint32_t bq[4][4];
            #pragma unroll
            for (int p = 0; p < 4; p++) {
                uint4 v;
                LDSM4(v, bufB + bBase + p * 2048 + bcol);
                bq[p][0] = v.x; bq[p][1] = v.y; bq[p][2] = v.z; bq[p][3] = v.w;
            }
            #pragma unroll
            for (int mt = 0; mt < 4; mt++) {
                uint4 v;
                LDSM4(v, bufA + aBase + mt * 2048 + acol);
                uint32_t af[4] = {v.x, v.y, v.z, v.w};
                #pragma unroll
                for (int p = 0; p < 4; p++) {
                    uint32_t b0[2] = {bq[p][0], bq[p][1]};
                    uint32_t b1[2] = {bq[p][2], bq[p][3]};
                    mma_f16(acc[mt][2 * p    ], af, b0);
                    mma_f16(acc[mt][2 * p + 1], af, b1);
                }
            }
        }
    }

    // Epilogue (thread fragment rows g,g+8; cols t*2,t*2+1)
    const int g = lane >> 2, t = lane & 3;
    const int region = (mode == 0) ? (blockIdx.x >> 2) : 0;
    #pragma unroll
    for (int mt = 0; mt < 4; mt++) {
        const int row = blockIdx.y * 128 + wm * 64 + mt * 16 + g;
        #pragma unroll
        for (int nt = 0; nt < 8; nt++) {
            const int col = blockIdx.x * 256 + wn * 64 + nt * 8 + t * 2;
            const float c0 = acc[mt][nt][0], c1 = acc[mt][nt][1];
            const float c2 = acc[mt][nt][2], c3 = acc[mt][nt][3];
            if (mode == 1) {
                float* Cp = C + sC * zb + koffC * zt;
                float2 lo = {c0 * scale, c1 * scale};
                float2 hi = {c2 * scale, c3 * scale};
                *reinterpret_cast<float2*>(Cp + (long long)row * N + col)       = lo;
                *reinterpret_cast<float2*>(Cp + (long long)(row + 8) * N + col) = hi;
            } else {
                const int bb = row >> 12;
                const int ss = row & 4095;
                const long long base = (long long)bb << 22;
                const float b0 = bias[col], b1 = bias[col + 1];
                if (region == 0) {
                    __half2 lo = __floats2half2_rn((c0 + b0) * 0.03125f, (c1 + b1) * 0.03125f);
                    __half2 hi = __floats2half2_rn((c2 + b0) * 0.03125f, (c3 + b1) * 0.03125f);
                    __half* dst = g_q + base + (long long)ss * 1024 + col;
                    *reinterpret_cast<__half2*>(dst)        = lo;
                    *reinterpret_cast<__half2*>(dst + 8192) = hi;
                } else if (region == 1) {
                    __half2 lo = __floats2half2_rn(c0 + b0, c1 + b1);
                    __half2 hi = __floats2half2_rn(c2 + b0, c3 + b1);
                    __half* dst = g_k + base + (long long)ss * 1024 + (col - 1024);
                    *reinterpret_cast<__half2*>(dst)        = lo;
                    *reinterpret_cast<__half2*>(dst + 8192) = hi;
                } else {
                    const int d = col - 2048;
                    __half* vt = g_vt + base + ss;
                    vt[(long long)d * 4096]           = __float2half_rn(c0 + b0);
                    vt[(long long)(d + 1) * 4096]     = __float2half_rn(c1 + b1);
                    vt[(long long)d * 4096 + 8]       = __float2half_rn(c2 + b0);
                    vt[(long long)(d + 1) * 4096 + 8] = __float2half_rn(c3 + b1);
                }
            }
        }
    }
}

// out = p0 + p1 (split-K reduction), float4.
__global__ __launch_bounds__(256) void reduce_add(float* __restrict__ out,
                                                  const float* __restrict__ p, int n4)
{
    int i = blockIdx.x * blockDim.x + threadIdx.x;
    if (i < n4) {
        float4 a = reinterpret_cast<const float4*>(p)[i];
        float4 b = reinterpret_cast<const float4*>(p + 16777216)[i];
        float4 o = {a.x + b.x, a.y + b.y, a.z + b.z, a.w + b.w};
        reinterpret_cast<float4*>(out)[i] = o;
    }
}

// f32 -> fp16 convert, 8 elements/thread.
__global__ __launch_bounds__(256) void to_half(__half* __restrict__ dst,
                                               const float* __restrict__ src, int n8)
{
    int i = blockIdx.x * blockDim.x + threadIdx.x;
    if (i < n8) {
        float4 a = reinterpret_cast<const float4*>(src)[2 * i];
        float4 b = reinterpret_cast<const float4*>(src)[2 * i + 1];
        __half2 h[4] = {__floats2half2_rn(a.x, a.y), __floats2half2_rn(a.z, a.w),
                        __floats2half2_rn(b.x, b.y), __floats2half2_rn(b.z, b.w)};
        reinterpret_cast<uint4*>(dst)[i] = *reinterpret_cast<uint4*>(h);
    }
}

// One block per row: softmax fp32 row -> fp16 probs row.
__global__ __launch_bounds__(256) void softmax_rows(const float* __restrict__ S,
                                                    __half* __restrict__ P)
{
    const float* p = S + (long long)blockIdx.x * 4096;
    __half* po     = P + (long long)blockIdx.x * 4096;
    const int tid  = threadIdx.x;
    const int warp = tid >> 5;
    const int lane = tid & 31;
    __shared__ float red[8];

    float4 v[4];
    float m = -3.4e38f;
    #pragma unroll
    for (int i = 0; i < 4; i++) {
        v[i] = reinterpret_cast<const float4*>(p)[tid + i * 256];
        m = fmaxf(m, fmaxf(fmaxf(v[i].x, v[i].y), fmaxf(v[i].z, v[i].w)));
    }
    #pragma unroll
    for (int o = 16; o > 0; o >>= 1) m = fmaxf(m, __shfl_xor_sync(0xffffffffu, m, o));
    if (lane == 0) red[warp] = m;
    __syncthreads();
    m = red[0];
    #pragma unroll
    for (int i = 1; i < 8; i++) m = fmaxf(m, red[i]);
    __syncthreads();

    float sum = 0.f;
    #pragma unroll
    for (int i = 0; i < 4; i++) {
        v[i].x = __expf(v[i].x - m); v[i].y = __expf(v[i].y - m);
        v[i].z = __expf(v[i].z - m); v[i].w = __expf(v[i].w - m);
        sum += v[i].x + v[i].y + v[i].z + v[i].w;
    }
    #pragma unroll
    for (int o = 16; o > 0; o >>= 1) sum += __shfl_xor_sync(0xffffffffu, sum, o);
    if (lane == 0) red[warp] = sum;
    __syncthreads();
    sum = red[0] + red[1] + red[2] + red[3] + red[4] + red[5] + red[6] + red[7];

    const float inv = 1.0f / sum;
    #pragma unroll
    for (int i = 0; i < 4; i++) {
        __half2 h[2] = {__floats2half2_rn(v[i].x * inv, v[i].y * inv),
                        __floats2half2_rn(v[i].z * inv, v[i].w * inv)};
        reinterpret_cast<uint2*>(po)[tid + i * 256] = *reinterpret_cast<uint2*>(h);
    }
}

extern "C" void kernel_launch(void* const* d_in, const int* in_sizes, int n_in,
                              void* d_out, int out_size)
{
    const float* X    = (const float*)d_in[0];
    const float* W    = (const float*)d_in[1];
    const float* bias = (const float*)d_in[2];
    float*       out  = (float*)d_out;

    __half *x, *w, *q, *k, *vt, *pp;
    float *s, *pt;
    cudaGetSymbolAddress((void**)&x,  g_x);
    cudaGetSymbolAddress((void**)&w,  g_w);
    cudaGetSymbolAddress((void**)&q,  g_q);
    cudaGetSymbolAddress((void**)&k,  g_k);
    cudaGetSymbolAddress((void**)&vt, g_vt);
    cudaGetSymbolAddress((void**)&s,  g_s);
    cudaGetSymbolAddress((void**)&pp, g_p);
    cudaGetSymbolAddress((void**)&pt, g_pt);

    static int once = 0;
    if (!once) {
        cudaFuncSetAttribute(gemm_tc, cudaFuncAttributeMaxDynamicSharedMemorySize, 196608);
        once = 1;
    }

    // 0) convert X, W to fp16
    to_half<<<8192, 256>>>(x, X, 16777216 / 8);
    to_half<<<1536, 256>>>(w, W,  3145728 / 8);

    // 1) QKV projection -> route Q/32, K, Vt (all fp16)
    gemm_tc<<<dim3(12, 128, 1), 256, 196608>>>(x, w, bias, nullptr,
                                               1024, 3072, 1024, 1024,
                                               0, 0, 0,
                                               0, 0, 0, 0,
                                               /*mode=*/0, 1.0f);
    // 2) Scores (fp32 out): per-batch [4096,1024] @ [4096,1024]^T
    gemm_tc<<<dim3(16, 32, 4), 256, 196608>>>(q, k, bias, s,
                                              1024, 4096, 1024, 1024,
                                              1LL << 22, 1LL << 22, 1LL << 24,
                                              2, 0, 0, 0,
                                              /*mode=*/1, 1.0f);
    // 3) Row softmax fp32 -> fp16 probs
    softmax_rows<<<16384, 256>>>(s, pp);
    // 4) PV partials: split-K=2, z = (t<<2)|batch
    gemm_tc<<<dim3(4, 32, 8), 256, 196608>>>(pp, vt, bias, pt,
                                             2048, 1024, 4096, 4096,
                                             1LL << 24, 1LL << 22, 1LL << 22,
                                             2, 2048, 2048, 16777216LL,
                                             /*mode=*/1, 1.0f);
    // 5) Reduce partials into final output
    reduce_add<<<16384, 256>>>(out, pt, 16777216 / 4);
}

// round 9
// speedup vs baseline: 5.3516x; 1.1572x over previous
#include <cuda_runtime.h>
#include <cuda_fp16.h>
#include <cstdint>

// ---------------------------------------------------------------------------
// SelfAttentionV2, round 8: fp16 mma.sync m16n8k16, CTA 128x128 (warp 64x32),
// 3-stage cp.async pipeline (32KB/stage, 96KB total) -> 2 CTAs/SM resident.
// No split-K (2 CTA slots cover PV wave quantization). Scores fp32,
// probs/X/W/Q/K/Vt fp16.
// ---------------------------------------------------------------------------

__device__ __half g_x [16777216];   // X  fp16
__device__ __half g_w [ 3145728];   // W  fp16
__device__ __half g_q [16777216];   // Q  fp16, pre-scaled 1/32
__device__ __half g_k [16777216];   // K  fp16
__device__ __half g_vt[16777216];   // V^T fp16 [b][d][s]
__device__ float  g_s [67108864];   // scores fp32 [b][q][k]
__device__ __half g_p [67108864];   // softmax probs fp16 [b][q][k]

__device__ __forceinline__ void mma_f16(float c[4], const uint32_t a[4], const uint32_t b[2]) {
    asm volatile(
        "mma.sync.aligned.m16n8k16.row.col.f32.f16.f16.f32 "
        "{%0,%1,%2,%3}, {%4,%5,%6,%7}, {%8,%9}, {%0,%1,%2,%3};"
        : "+f"(c[0]), "+f"(c[1]), "+f"(c[2]), "+f"(c[3])
        : "r"(a[0]), "r"(a[1]), "r"(a[2]), "r"(a[3]), "r"(b[0]), "r"(b[1]));
}

#define LDSM4(v, addr)                                                     \
    asm volatile("ldmatrix.sync.aligned.m8n8.x4.shared.b16 {%0,%1,%2,%3}, [%4];" \
                 : "=r"((v).x), "=r"((v).y), "=r"((v).z), "=r"((v).w) : "r"(addr))

#define CPA16(sm, gm)                                                      \
    asm volatile("cp.async.cg.shared.global [%0], [%1], 16;"               \
                 :: "r"(sm), "l"(gm) : "memory")

// Smem tiles: K-major fp16 rows of 64 halves = 128B, SW128 swizzle:
// chunk(r, j) at byte (r*128 + j*16) ^ ((r&7)<<4).
// Stage (32KB): A[0,16K) = 128 rows, B[16K,32K) = 128 rows. 3 stages.

__global__ __launch_bounds__(256, 2) void gemm_tc(
    const __half* __restrict__ A, const __half* __restrict__ B,
    const float* __restrict__ bias, float* __restrict__ C,
    int K, int N, int lda, int ldb,
    long long sA, long long sB, long long sC,
    int mode, float scale)
{
    extern __shared__ __align__(1024) uint8_t smem[];   // 3 x 32KB
    const uint32_t sb = (uint32_t)__cvta_generic_to_shared(smem);
    const int tid  = threadIdx.x;
    const int warp = tid >> 5;
    const int lane = tid & 31;
    const int wm = warp & 1, wn = warp >> 1;   // warp tile 64(m) x 32(n)

    // ldmatrix lane roles (bytes)
    const uint32_t xorr  = (uint32_t)(lane & 7) << 4;
    const uint32_t aBase = (uint32_t)(wm * 64 + (lane & 15)) * 128;
    const uint32_t kselA = (uint32_t)(lane >> 4) << 4;
    const uint32_t bBase = (uint32_t)(wn * 32 + ((lane >> 4) << 3) + (lane & 7)) * 128;
    const uint32_t kselB = (uint32_t)((lane >> 3) & 1) << 4;

    const __half* Ab = A + sA * blockIdx.z + (long long)blockIdx.y * 128 * lda;
    const __half* Bb = B + sB * blockIdx.z + (long long)blockIdx.x * 128 * ldb;

    float acc[4][4][4] = {};
    const int ns = K >> 6;     // 64 halves per slice

    #define ISSUE(S)                                                          \
    do {                                                                      \
        const uint32_t ba = sb + ((S) % 3) * 32768;                           \
        const int k0 = (S) << 6;                                              \
        _Pragma("unroll")                                                     \
        for (int i = 0; i < 4; i++) {                                         \
            int id = tid + i * 256, r = id >> 3, j = id & 7;                  \
            uint32_t so = ((uint32_t)(r * 128 + j * 16)) ^ ((uint32_t)(r & 7) << 4); \
            CPA16(ba + so, Ab + (long long)r * lda + k0 + j * 8);             \
        }                                                                     \
        _Pragma("unroll")                                                     \
        for (int i = 0; i < 4; i++) {                                         \
            int id = tid + i * 256, r = id >> 3, j = id & 7;                  \
            uint32_t so = ((uint32_t)(r * 128 + j * 16)) ^ ((uint32_t)(r & 7) << 4); \
            CPA16(ba + 16384 + so, Bb + (long long)r * ldb + k0 + j * 8);     \
        }                                                                     \
        asm volatile("cp.async.commit_group;" ::: "memory");                  \
    } while (0)

    ISSUE(0);
    if (ns > 1) ISSUE(1);

    for (int s = 0; s < ns; s++) {
        if (s + 1 < ns) asm volatile("cp.async.wait_group 1;" ::: "memory");
        else            asm volatile("cp.async.wait_group 0;" ::: "memory");
        __syncthreads();
        if (s + 2 < ns) ISSUE(s + 2);   // writes buf (s+2)%3: retired at this barrier

        const uint32_t bufA = sb + (s % 3) * 32768;
        const uint32_t bufB = bufA + 16384;
        #pragma unroll
        for (int kk = 0; kk < 4; kk++) {                 // K=16 halves per kk
            const uint32_t acol = (((uint32_t)kk << 5) + kselA) ^ xorr;
            const uint32_t bcol = (((uint32_t)kk << 5) + kselB) ^ xorr;
            uint32_t bq[2][4];
            #pragma unroll
            for (int p = 0; p < 2; p++) {
                uint4 v;
                LDSM4(v, bufB + bBase + p * 2048 + bcol);
                bq[p][0] = v.x; bq[p][1] = v.y; bq[p][2] = v.z; bq[p][3] = v.w;
            }
            #pragma unroll
            for (int mt = 0; mt < 4; mt++) {
                uint4 v;
                LDSM4(v, bufA + aBase + mt * 2048 + acol);
                uint32_t af[4] = {v.x, v.y, v.z, v.w};
                #pragma unroll
                for (int p = 0; p < 2; p++) {
                    uint32_t b0[2] = {bq[p][0], bq[p][1]};
                    uint32_t b1[2] = {bq[p][2], bq[p][3]};
                    mma_f16(acc[mt][2 * p    ], af, b0);
                    mma_f16(acc[mt][2 * p + 1], af, b1);
                }
            }
        }
    }

    // Epilogue (thread fragment rows g,g+8; cols t*2,t*2+1)
    const int g = lane >> 2, t = lane & 3;
    const int region = (mode == 0) ? (blockIdx.x >> 3) : 0;   // 8 blocks per 1024 cols
    #pragma unroll
    for (int mt = 0; mt < 4; mt++) {
        const int row = blockIdx.y * 128 + wm * 64 + mt * 16 + g;
        #pragma unroll
        for (int nt = 0; nt < 4; nt++) {
            const int col = blockIdx.x * 128 + wn * 32 + nt * 8 + t * 2;
            const float c0 = acc[mt][nt][0], c1 = acc[mt][nt][1];
            const float c2 = acc[mt][nt][2], c3 = acc[mt][nt][3];
            if (mode == 1) {
                float* Cp = C + sC * blockIdx.z;
                float2 lo = {c0 * scale, c1 * scale};
                float2 hi = {c2 * scale, c3 * scale};
                *reinterpret_cast<float2*>(Cp + (long long)row * N + col)       = lo;
                *reinterpret_cast<float2*>(Cp + (long long)(row + 8) * N + col) = hi;
            } else {
                const int bb = row >> 12;
                const int ss = row & 4095;
                const long long base = (long long)bb << 22;
                const float b0 = bias[col], b1 = bias[col + 1];
                if (region == 0) {
                    __half2 lo = __floats2half2_rn((c0 + b0) * 0.03125f, (c1 + b1) * 0.03125f);
                    __half2 hi = __floats2half2_rn((c2 + b0) * 0.03125f, (c3 + b1) * 0.03125f);
                    __half* dst = g_q + base + (long long)ss * 1024 + col;
                    *reinterpret_cast<__half2*>(dst)        = lo;
                    *reinterpret_cast<__half2*>(dst + 8192) = hi;
                } else if (region == 1) {
                    __half2 lo = __floats2half2_rn(c0 + b0, c1 + b1);
                    __half2 hi = __floats2half2_rn(c2 + b0, c3 + b1);
                    __half* dst = g_k + base + (long long)ss * 1024 + (col - 1024);
                    *reinterpret_cast<__half2*>(dst)        = lo;
                    *reinterpret_cast<__half2*>(dst + 8192) = hi;
                } else {
                    const int d = col - 2048;
                    __half* vt = g_vt + base + ss;
                    vt[(long long)d * 4096]           = __float2half_rn(c0 + b0);
                    vt[(long long)(d + 1) * 4096]     = __float2half_rn(c1 + b1);
                    vt[(long long)d * 4096 + 8]       = __float2half_rn(c2 + b0);
                    vt[(long long)(d + 1) * 4096 + 8] = __float2half_rn(c3 + b1);
                }
            }
        }
    }
}

// f32 -> fp16 convert, 8 elements/thread.
__global__ __launch_bounds__(256) void to_half(__half* __restrict__ dst,
                                               const float* __restrict__ src, int n8)
{
    int i = blockIdx.x * blockDim.x + threadIdx.x;
    if (i < n8) {
        float4 a = reinterpret_cast<const float4*>(src)[2 * i];
        float4 b = reinterpret_cast<const float4*>(src)[2 * i + 1];
        __half2 h[4] = {__floats2half2_rn(a.x, a.y), __floats2half2_rn(a.z, a.w),
                        __floats2half2_rn(b.x, b.y), __floats2half2_rn(b.z, b.w)};
        reinterpret_cast<uint4*>(dst)[i] = *reinterpret_cast<uint4*>(h);
    }
}

// One block per row: softmax fp32 row -> fp16 probs row.
__global__ __launch_bounds__(256) void softmax_rows(const float* __restrict__ S,
                                                    __half* __restrict__ P)
{
    const float* p = S + (long long)blockIdx.x * 4096;
    __half* po     = P + (long long)blockIdx.x * 4096;
    const int tid  = threadIdx.x;
    const int warp = tid >> 5;
    const int lane = tid & 31;
    __shared__ float red[8];

    float4 v[4];
    float m = -3.4e38f;
    #pragma unroll
    for (int i = 0; i < 4; i++) {
        v[i] = reinterpret_cast<const float4*>(p)[tid + i * 256];
        m = fmaxf(m, fmaxf(fmaxf(v[i].x, v[i].y), fmaxf(v[i].z, v[i].w)));
    }
    #pragma unroll
    for (int o = 16; o > 0; o >>= 1) m = fmaxf(m, __shfl_xor_sync(0xffffffffu, m, o));
    if (lane == 0) red[warp] = m;
    __syncthreads();
    m = red[0];
    #pragma unroll
    for (int i = 1; i < 8; i++) m = fmaxf(m, red[i]);
    __syncthreads();

    float sum = 0.f;
    #pragma unroll
    for (int i = 0; i < 4; i++) {
        v[i].x = __expf(v[i].x - m); v[i].y = __expf(v[i].y - m);
        v[i].z = __expf(v[i].z - m); v[i].w = __expf(v[i].w - m);
        sum += v[i].x + v[i].y + v[i].z + v[i].w;
    }
    #pragma unroll
    for (int o = 16; o > 0; o >>= 1) sum += __shfl_xor_sync(0xffffffffu, sum, o);
    if (lane == 0) red[warp] = sum;
    __syncthreads();
    sum = red[0] + red[1] + red[2] + red[3] + red[4] + red[5] + red[6] + red[7];

    const float inv = 1.0f / sum;
    #pragma unroll
    for (int i = 0; i < 4; i++) {
        __half2 h[2] = {__floats2half2_rn(v[i].x * inv, v[i].y * inv),
                        __floats2half2_rn(v[i].z * inv, v[i].w * inv)};
        reinterpret_cast<uint2*>(po)[tid + i * 256] = *reinterpret_cast<uint2*>(h);
    }
}

extern "C" void kernel_launch(void* const* d_in, const int* in_sizes, int n_in,
                              void* d_out, int out_size)
{
    const float* X    = (const float*)d_in[0];
    const float* W    = (const float*)d_in[1];
    const float* bias = (const float*)d_in[2];
    float*       out  = (float*)d_out;

    __half *x, *w, *q, *k, *vt, *pp;
    float *s;
    cudaGetSymbolAddress((void**)&x,  g_x);
    cudaGetSymbolAddress((void**)&w,  g_w);
    cudaGetSymbolAddress((void**)&q,  g_q);
    cudaGetSymbolAddress((void**)&k,  g_k);
    cudaGetSymbolAddress((void**)&vt, g_vt);
    cudaGetSymbolAddress((void**)&s,  g_s);
    cudaGetSymbolAddress((void**)&pp, g_p);

    static int once = 0;
    if (!once) {
        cudaFuncSetAttribute(gemm_tc, cudaFuncAttributeMaxDynamicSharedMemorySize, 98304);
        once = 1;
    }

    // 0) convert X, W to fp16
    to_half<<<8192, 256>>>(x, X, 16777216 / 8);
    to_half<<<1536, 256>>>(w, W,  3145728 / 8);

    // 1) QKV projection -> route Q/32, K, Vt (all fp16)
    gemm_tc<<<dim3(24, 128, 1), 256, 98304>>>(x, w, bias, nullptr,
                                              1024, 3072, 1024, 1024,
                                              0, 0, 0,
                                              /*mode=*/0, 1.0f);
    // 2) Scores (fp32 out): per-batch [4096,1024] @ [4096,1024]^T
    gemm_tc<<<dim3(32, 32, 4), 256, 98304>>>(q, k, bias, s,
                                             1024, 4096, 1024, 1024,
                                             1LL << 22, 1LL << 22, 1LL << 24,
                                             /*mode=*/1, 1.0f);
    // 3) Row softmax fp32 -> fp16 probs
    softmax_rows<<<16384, 256>>>(s, pp);
    // 4) Output: per-batch [4096,4096] @ [1024,4096]^T directly into out
    gemm_tc<<<dim3(8, 32, 4), 256, 98304>>>(pp, vt, bias, out,
                                            4096, 1024, 4096, 4096,
                                            1LL << 24, 1LL << 22, 1LL << 22,
                                            /*mode=*/1, 1.0f);
}

// round 11
// speedup vs baseline: 5.4228x; 1.0133x over previous
#include <cuda_runtime.h>
#include <cuda_fp16.h>
#include <cstdint>

// ---------------------------------------------------------------------------
// SelfAttentionV2, round 9: fp16 mma.sync m16n8k16, CTA 128x128 (warp 64x32),
// 3-stage cp.async pipeline, 2 CTAs/SM. NEW: scores stored fp16 (mode 2
// epilogue) and softmax runs fp16 in / fp16 out -> 384 MB less DRAM traffic.
// ---------------------------------------------------------------------------

__device__ __half g_x [16777216];   // X  fp16
__device__ __half g_w [ 3145728];   // W  fp16
__device__ __half g_q [16777216];   // Q  fp16, pre-scaled 1/32
__device__ __half g_k [16777216];   // K  fp16
__device__ __half g_vt[16777216];   // V^T fp16 [b][d][s]
__device__ __half g_s [67108864];   // scores fp16 [b][q][k]
__device__ __half g_p [67108864];   // softmax probs fp16 [b][q][k]

__device__ __forceinline__ void mma_f16(float c[4], const uint32_t a[4], const uint32_t b[2]) {
    asm volatile(
        "mma.sync.aligned.m16n8k16.row.col.f32.f16.f16.f32 "
        "{%0,%1,%2,%3}, {%4,%5,%6,%7}, {%8,%9}, {%0,%1,%2,%3};"
        : "+f"(c[0]), "+f"(c[1]), "+f"(c[2]), "+f"(c[3])
        : "r"(a[0]), "r"(a[1]), "r"(a[2]), "r"(a[3]), "r"(b[0]), "r"(b[1]));
}

#define LDSM4(v, addr)                                                     \
    asm volatile("ldmatrix.sync.aligned.m8n8.x4.shared.b16 {%0,%1,%2,%3}, [%4];" \
                 : "=r"((v).x), "=r"((v).y), "=r"((v).z), "=r"((v).w) : "r"(addr))

#define CPA16(sm, gm)                                                      \
    asm volatile("cp.async.cg.shared.global [%0], [%1], 16;"               \
                 :: "r"(sm), "l"(gm) : "memory")

// Smem tiles: K-major fp16 rows of 64 halves = 128B, SW128 swizzle:
// chunk(r, j) at byte (r*128 + j*16) ^ ((r&7)<<4).
// Stage (32KB): A[0,16K) = 128 rows, B[16K,32K) = 128 rows. 3 stages.

// mode 0: QKV route epilogue (bias, Q/32, K, Vt; all fp16 out)
// mode 1: C fp32 = acc * scale
// mode 2: C fp16 = acc * scale   (C cast to __half*, sC in half elements)
__global__ __launch_bounds__(256, 2) void gemm_tc(
    const __half* __restrict__ A, const __half* __restrict__ B,
    const float* __restrict__ bias, float* __restrict__ C,
    int K, int N, int lda, int ldb,
    long long sA, long long sB, long long sC,
    int mode, float scale)
{
    extern __shared__ __align__(1024) uint8_t smem[];   // 3 x 32KB
    const uint32_t sb = (uint32_t)__cvta_generic_to_shared(smem);
    const int tid  = threadIdx.x;
    const int warp = tid >> 5;
    const int lane = tid & 31;
    const int wm = warp & 1, wn = warp >> 1;   // warp tile 64(m) x 32(n)

    // ldmatrix lane roles (bytes)
    const uint32_t xorr  = (uint32_t)(lane & 7) << 4;
    const uint32_t aBase = (uint32_t)(wm * 64 + (lane & 15)) * 128;
    const uint32_t kselA = (uint32_t)(lane >> 4) << 4;
    const uint32_t bBase = (uint32_t)(wn * 32 + ((lane >> 4) << 3) + (lane & 7)) * 128;
    const uint32_t kselB = (uint32_t)((lane >> 3) & 1) << 4;

    const __half* Ab = A + sA * blockIdx.z + (long long)blockIdx.y * 128 * lda;
    const __half* Bb = B + sB * blockIdx.z + (long long)blockIdx.x * 128 * ldb;

    float acc[4][4][4] = {};
    const int ns = K >> 6;     // 64 halves per slice

    #define ISSUE(S)                                                          \
    do {                                                                      \
        const uint32_t ba = sb + ((S) % 3) * 32768;                           \
        const int k0 = (S) << 6;                                              \
        _Pragma("unroll")                                                     \
        for (int i = 0; i < 4; i++) {                                         \
            int id = tid + i * 256, r = id >> 3, j = id & 7;                  \
            uint32_t so = ((uint32_t)(r * 128 + j * 16)) ^ ((uint32_t)(r & 7) << 4); \
            CPA16(ba + so, Ab + (long long)r * lda + k0 + j * 8);             \
        }                                                                     \
        _Pragma("unroll")                                                     \
        for (int i = 0; i < 4; i++) {                                         \
            int id = tid + i * 256, r = id >> 3, j = id & 7;                  \
            uint32_t so = ((uint32_t)(r * 128 + j * 16)) ^ ((uint32_t)(r & 7) << 4); \
            CPA16(ba + 16384 + so, Bb + (long long)r * ldb + k0 + j * 8);     \
        }                                                                     \
        asm volatile("cp.async.commit_group;" ::: "memory");                  \
    } while (0)

    ISSUE(0);
    if (ns > 1) ISSUE(1);

    for (int s = 0; s < ns; s++) {
        if (s + 1 < ns) asm volatile("cp.async.wait_group 1;" ::: "memory");
        else            asm volatile("cp.async.wait_group 0;" ::: "memory");
        __syncthreads();
        if (s + 2 < ns) ISSUE(s + 2);   // writes buf (s+2)%3: retired at this barrier

        const uint32_t bufA = sb + (s % 3) * 32768;
        const uint32_t bufB = bufA + 16384;
        #pragma unroll
        for (int kk = 0; kk < 4; kk++) {                 // K=16 halves per kk
            const uint32_t acol = (((uint32_t)kk << 5) + kselA) ^ xorr;
            const uint32_t bcol = (((uint32_t)kk << 5) + kselB) ^ xorr;
            uint32_t bq[2][4];
            #pragma unroll
            for (int p = 0; p < 2; p++) {
                uint4 v;
                LDSM4(v, bufB + bBase + p * 2048 + bcol);
                bq[p][0] = v.x; bq[p][1] = v.y; bq[p][2] = v.z; bq[p][3] = v.w;
            }
            #pragma unroll
            for (int mt = 0; mt < 4; mt++) {
                uint4 v;
                LDSM4(v, bufA + aBase + mt * 2048 + acol);
                uint32_t af[4] = {v.x, v.y, v.z, v.w};
                #pragma unroll
                for (int p = 0; p < 2; p++) {
                    uint32_t b0[2] = {bq[p][0], bq[p][1]};
                    uint32_t b1[2] = {bq[p][2], bq[p][3]};
                    mma_f16(acc[mt][2 * p    ], af, b0);
                    mma_f16(acc[mt][2 * p + 1], af, b1);
                }
            }
        }
    }

    // Epilogue (thread fragment rows g,g+8; cols t*2,t*2+1)
    const int g = lane >> 2, t = lane & 3;
    const int region = (mode == 0) ? (blockIdx.x >> 3) : 0;   // 8 blocks per 1024 cols
    #pragma unroll
    for (int mt = 0; mt < 4; mt++) {
        const int row = blockIdx.y * 128 + wm * 64 + mt * 16 + g;
        #pragma unroll
        for (int nt = 0; nt < 4; nt++) {
            const int col = blockIdx.x * 128 + wn * 32 + nt * 8 + t * 2;
            const float c0 = acc[mt][nt][0], c1 = acc[mt][nt][1];
            const float c2 = acc[mt][nt][2], c3 = acc[mt][nt][3];
            if (mode == 1) {
                float* Cp = C + sC * blockIdx.z;
                float2 lo = {c0 * scale, c1 * scale};
                float2 hi = {c2 * scale, c3 * scale};
                *reinterpret_cast<float2*>(Cp + (long long)row * N + col)       = lo;
                *reinterpret_cast<float2*>(Cp + (long long)(row + 8) * N + col) = hi;
            } else if (mode == 2) {
                __half* Cp = reinterpret_cast<__half*>(C) + sC * blockIdx.z;
                *reinterpret_cast<__half2*>(Cp + (long long)row * N + col) =
                    __floats2half2_rn(c0 * scale, c1 * scale);
                *reinterpret_cast<__half2*>(Cp + (long long)(row + 8) * N + col) =
                    __floats2half2_rn(c2 * scale, c3 * scale);
            } else {
                const int bb = row >> 12;
                const int ss = row & 4095;
                const long long base = (long long)bb << 22;
                const float b0 = bias[col], b1 = bias[col + 1];
                if (region == 0) {
                    __half2 lo = __floats2half2_rn((c0 + b0) * 0.03125f, (c1 + b1) * 0.03125f);
                    __half2 hi = __floats2half2_rn((c2 + b0) * 0.03125f, (c3 + b1) * 0.03125f);
                    __half* dst = g_q + base + (long long)ss * 1024 + col;
                    *reinterpret_cast<__half2*>(dst)        = lo;
                    *reinterpret_cast<__half2*>(dst + 8192) = hi;
                } else if (region == 1) {
                    __half2 lo = __floats2half2_rn(c0 + b0, c1 + b1);
                    __half2 hi = __floats2half2_rn(c2 + b0, c3 + b1);
                    __half* dst = g_k + base + (long long)ss * 1024 + (col - 1024);
                    *reinterpret_cast<__half2*>(dst)        = lo;
                    *reinterpret_cast<__half2*>(dst + 8192) = hi;
                } else {
                    const int d = col - 2048;
                    __half* vt = g_vt + base + ss;
                    vt[(long long)d * 4096]           = __float2half_rn(c0 + b0);
                    vt[(long long)(d + 1) * 4096]     = __float2half_rn(c1 + b1);
                    vt[(long long)d * 4096 + 8]       = __float2half_rn(c2 + b0);
                    vt[(long long)(d + 1) * 4096 + 8] = __float2half_rn(c3 + b1);
                }
            }
        }
    }
}

// f32 -> fp16 convert, 8 elements/thread.
__global__ __launch_bounds__(256) void to_half(__half* __restrict__ dst,
                                               const float* __restrict__ src, int n8)
{
    int i = blockIdx.x * blockDim.x + threadIdx.x;
    if (i < n8) {
        float4 a = reinterpret_cast<const float4*>(src)[2 * i];
        float4 b = reinterpret_cast<const float4*>(src)[2 * i + 1];
        __half2 h[4] = {__floats2half2_rn(a.x, a.y), __floats2half2_rn(a.z, a.w),
                        __floats2half2_rn(b.x, b.y), __floats2half2_rn(b.z, b.w)};
        reinterpret_cast<uint4*>(dst)[i] = *reinterpret_cast<uint4*>(h);
    }
}

// One block per row: softmax over 4096 fp16 scores -> fp16 probs.
// 256 threads x 16 halves (2 uint4 loads / 2 uint4 stores per thread).
__global__ __launch_bounds__(256) void softmax_rows(const __half* __restrict__ S,
                                                    __half* __restrict__ P)
{
    const __half* p = S + (long long)blockIdx.x * 4096;
    __half* po      = P + (long long)blockIdx.x * 4096;
    const int tid  = threadIdx.x;
    const int warp = tid >> 5;
    const int lane = tid & 31;
    __shared__ float red[8];

    float v[16];
    #pragma unroll
    for (int u = 0; u < 2; u++) {
        uint4 raw = reinterpret_cast<const uint4*>(p)[tid * 2 + u];
        const uint32_t* rw = reinterpret_cast<const uint32_t*>(&raw);
        #pragma unroll
        for (int j = 0; j < 4; j++) {
            float2 f = __half22float2(*reinterpret_cast<const __half2*>(&rw[j]));
            v[u * 8 + j * 2]     = f.x;
            v[u * 8 + j * 2 + 1] = f.y;
        }
    }

    float m = -3.4e38f;
    #pragma unroll
    for (int j = 0; j < 16; j++) m = fmaxf(m, v[j]);
    #pragma unroll
    for (int o = 16; o > 0; o >>= 1) m = fmaxf(m, __shfl_xor_sync(0xffffffffu, m, o));
    if (lane == 0) red[warp] = m;
    __syncthreads();
    m = red[0];
    #pragma unroll
    for (int i = 1; i < 8; i++) m = fmaxf(m, red[i]);
    __syncthreads();

    float sum = 0.f;
    #pragma unroll
    for (int j = 0; j < 16; j++) { v[j] = __expf(v[j] - m); sum += v[j]; }
    #pragma unroll
    for (int o = 16; o > 0; o >>= 1) sum += __shfl_xor_sync(0xffffffffu, sum, o);
    if (lane == 0) red[warp] = sum;
    __syncthreads();
    sum = red[0] + red[1] + red[2] + red[3] + red[4] + red[5] + red[6] + red[7];

    const float inv = 1.0f / sum;
    #pragma unroll
    for (int u = 0; u < 2; u++) {
        __half2 h[4];
        #pragma unroll
        for (int j = 0; j < 4; j++)
            h[j] = __floats2half2_rn(v[u * 8 + j * 2] * inv, v[u * 8 + j * 2 + 1] * inv);
        reinterpret_cast<uint4*>(po)[tid * 2 + u] = *reinterpret_cast<uint4*>(h);
    }
}

extern "C" void kernel_launch(void* const* d_in, const int* in_sizes, int n_in,
                              void* d_out, int out_size)
{
    const float* X    = (const float*)d_in[0];
    const float* W    = (const float*)d_in[1];
    const float* bias = (const float*)d_in[2];
    float*       out  = (float*)d_out;

    __half *x, *w, *q, *k, *vt, *s, *pp;
    cudaGetSymbolAddress((void**)&x,  g_x);
    cudaGetSymbolAddress((void**)&w,  g_w);
    cudaGetSymbolAddress((void**)&q,  g_q);
    cudaGetSymbolAddress((void**)&k,  g_k);
    cudaGetSymbolAddress((void**)&vt, g_vt);
    cudaGetSymbolAddress((void**)&s,  g_s);
    cudaGetSymbolAddress((void**)&pp, g_p);

    static int once = 0;
    if (!once) {
        cudaFuncSetAttribute(gemm_tc, cudaFuncAttributeMaxDynamicSharedMemorySize, 98304);
        once = 1;
    }

    // 0) convert X, W to fp16
    to_half<<<8192, 256>>>(x, X, 16777216 / 8);
    to_half<<<1536, 256>>>(w, W,  3145728 / 8);

    // 1) QKV projection -> route Q/32, K, Vt (all fp16)
    gemm_tc<<<dim3(24, 128, 1), 256, 98304>>>(x, w, bias, nullptr,
                                              1024, 3072, 1024, 1024,
                                              0, 0, 0,
                                              /*mode=*/0, 1.0f);
    // 2) Scores (fp16 out): per-batch [4096,1024] @ [4096,1024]^T
    gemm_tc<<<dim3(32, 32, 4), 256, 98304>>>(q, k, bias, (float*)s,
                                             1024, 4096, 1024, 1024,
                                             1LL << 22, 1LL << 22, 1LL << 24,
                                             /*mode=*/2, 1.0f);
    // 3) Row softmax fp16 -> fp16 probs
    softmax_rows<<<16384, 256>>>(s, pp);
    // 4) Output: per-batch [4096,4096] @ [1024,4096]^T -> fp32 out
    gemm_tc<<<dim3(8, 32, 4), 256, 98304>>>(pp, vt, bias, out,
                                            4096, 1024, 4096, 4096,
                                            1LL << 24, 1LL << 22, 1LL << 22,
                                            /*mode=*/1, 1.0f);
}

// round 12
// speedup vs baseline: 5.4328x; 1.0019x over previous
#include <cuda_runtime.h>
#include <cuda_fp16.h>
#include <cstdint>

// ---------------------------------------------------------------------------
// SelfAttentionV2, round 12: fp16 mma.sync m16n8k16, CTA 128x128 (warp 64x32),
// 3-stage cp.async pipeline, 2 CTAs/SM. NEW: per-warp kk rotation to
// de-correlate LDSM bursts / MMA phases across warps after each barrier.
// Merged streaming to_half. Scores fp16 round-trip.
// ---------------------------------------------------------------------------

__device__ __half g_x [16777216];   // X  fp16
__device__ __half g_w [ 3145728];   // W  fp16
__device__ __half g_q [16777216];   // Q  fp16, pre-scaled 1/32
__device__ __half g_k [16777216];   // K  fp16
__device__ __half g_vt[16777216];   // V^T fp16 [b][d][s]
__device__ __half g_s [67108864];   // scores fp16 [b][q][k]
__device__ __half g_p [67108864];   // softmax probs fp16 [b][q][k]

__device__ __forceinline__ void mma_f16(float c[4], const uint32_t a[4], const uint32_t b[2]) {
    asm volatile(
        "mma.sync.aligned.m16n8k16.row.col.f32.f16.f16.f32 "
        "{%0,%1,%2,%3}, {%4,%5,%6,%7}, {%8,%9}, {%0,%1,%2,%3};"
        : "+f"(c[0]), "+f"(c[1]), "+f"(c[2]), "+f"(c[3])
        : "r"(a[0]), "r"(a[1]), "r"(a[2]), "r"(a[3]), "r"(b[0]), "r"(b[1]));
}

#define LDSM4(v, addr)                                                     \
    asm volatile("ldmatrix.sync.aligned.m8n8.x4.shared.b16 {%0,%1,%2,%3}, [%4];" \
                 : "=r"((v).x), "=r"((v).y), "=r"((v).z), "=r"((v).w) : "r"(addr))

#define CPA16(sm, gm)                                                      \
    asm volatile("cp.async.cg.shared.global [%0], [%1], 16;"               \
                 :: "r"(sm), "l"(gm) : "memory")

// Smem tiles: K-major fp16 rows of 64 halves = 128B, SW128 swizzle:
// chunk(r, j) at byte (r*128 + j*16) ^ ((r&7)<<4).
// Stage (32KB): A[0,16K) = 128 rows, B[16K,32K) = 128 rows. 3 stages.

// mode 0: QKV route epilogue (bias, Q/32, K, Vt; all fp16 out)
// mode 1: C fp32 = acc * scale
// mode 2: C fp16 = acc * scale   (C cast to __half*, sC in half elements)
__global__ __launch_bounds__(256, 2) void gemm_tc(
    const __half* __restrict__ A, const __half* __restrict__ B,
    const float* __restrict__ bias, float* __restrict__ C,
    int K, int N, int lda, int ldb,
    long long sA, long long sB, long long sC,
    int mode, float scale)
{
    extern __shared__ __align__(1024) uint8_t smem[];   // 3 x 32KB
    const uint32_t sb = (uint32_t)__cvta_generic_to_shared(smem);
    const int tid  = threadIdx.x;
    const int warp = tid >> 5;
    const int lane = tid & 31;
    const int wm = warp & 1, wn = warp >> 1;   // warp tile 64(m) x 32(n)

    // ldmatrix lane roles (bytes)
    const uint32_t xorr  = (uint32_t)(lane & 7) << 4;
    const uint32_t aBase = (uint32_t)(wm * 64 + (lane & 15)) * 128;
    const uint32_t kselA = (uint32_t)(lane >> 4) << 4;
    const uint32_t bBase = (uint32_t)(wn * 32 + ((lane >> 4) << 3) + (lane & 7)) * 128;
    const uint32_t kselB = (uint32_t)((lane >> 3) & 1) << 4;

    const __half* Ab = A + sA * blockIdx.z + (long long)blockIdx.y * 128 * lda;
    const __half* Bb = B + sB * blockIdx.z + (long long)blockIdx.x * 128 * ldb;

    float acc[4][4][4] = {};
    const int ns = K >> 6;     // 64 halves per slice

    #define ISSUE(S)                                                          \
    do {                                                                      \
        const uint32_t ba = sb + ((S) % 3) * 32768;                           \
        const int k0 = (S) << 6;                                              \
        _Pragma("unroll")                                                     \
        for (int i = 0; i < 4; i++) {                                         \
            int id = tid + i * 256, r = id >> 3, j = id & 7;                  \
            uint32_t so = ((uint32_t)(r * 128 + j * 16)) ^ ((uint32_t)(r & 7) << 4); \
            CPA16(ba + so, Ab + (long long)r * lda + k0 + j * 8);             \
        }                                                                     \
        _Pragma("unroll")                                                     \
        for (int i = 0; i < 4; i++) {                                         \
            int id = tid + i * 256, r = id >> 3, j = id & 7;                  \
            uint32_t so = ((uint32_t)(r * 128 + j * 16)) ^ ((uint32_t)(r & 7) << 4); \
            CPA16(ba + 16384 + so, Bb + (long long)r * ldb + k0 + j * 8);     \
        }                                                                     \
        asm volatile("cp.async.commit_group;" ::: "memory");                  \
    } while (0)

    ISSUE(0);
    if (ns > 1) ISSUE(1);

    for (int s = 0; s < ns; s++) {
        if (s + 1 < ns) asm volatile("cp.async.wait_group 1;" ::: "memory");
        else            asm volatile("cp.async.wait_group 0;" ::: "memory");
        __syncthreads();
        if (s + 2 < ns) ISSUE(s + 2);   // writes buf (s+2)%3: retired at this barrier

        const uint32_t bufA = sb + (s % 3) * 32768;
        const uint32_t bufB = bufA + 16384;
        // kk rotation: warp w starts at kk = w&3 so LDSM bursts and MMA
        // phases of the 16 resident warps are staggered after the barrier.
        #pragma unroll
        for (int kki = 0; kki < 4; kki++) {
            const int kk = (kki + warp) & 3;             // K=16 halves per kk
            const uint32_t acol = (((uint32_t)kk << 5) + kselA) ^ xorr;
            const uint32_t bcol = (((uint32_t)kk << 5) + kselB) ^ xorr;
            uint32_t bq[2][4];
            #pragma unroll
            for (int p = 0; p < 2; p++) {
                uint4 v;
                LDSM4(v, bufB + bBase + p * 2048 + bcol);
                bq[p][0] = v.x; bq[p][1] = v.y; bq[p][2] = v.z; bq[p][3] = v.w;
            }
            #pragma unroll
            for (int mt = 0; mt < 4; mt++) {
                uint4 v;
                LDSM4(v, bufA + aBase + mt * 2048 + acol);
                uint32_t af[4] = {v.x, v.y, v.z, v.w};
                #pragma unroll
                for (int p = 0; p < 2; p++) {
                    uint32_t b0[2] = {bq[p][0], bq[p][1]};
                    uint32_t b1[2] = {bq[p][2], bq[p][3]};
                    mma_f16(acc[mt][2 * p    ], af, b0);
                    mma_f16(acc[mt][2 * p + 1], af, b1);
                }
            }
        }
    }

    // Epilogue (thread fragment rows g,g+8; cols t*2,t*2+1)
    const int g = lane >> 2, t = lane & 3;
    const int region = (mode == 0) ? (blockIdx.x >> 3) : 0;   // 8 blocks per 1024 cols
    #pragma unroll
    for (int mt = 0; mt < 4; mt++) {
        const int row = blockIdx.y * 128 + wm * 64 + mt * 16 + g;
        #pragma unroll
        for (int nt = 0; nt < 4; nt++) {
            const int col = blockIdx.x * 128 + wn * 32 + nt * 8 + t * 2;
            const float c0 = acc[mt][nt][0], c1 = acc[mt][nt][1];
            const float c2 = acc[mt][nt][2], c3 = acc[mt][nt][3];
            if (mode == 1) {
                float* Cp = C + sC * blockIdx.z;
                float2 lo = {c0 * scale, c1 * scale};
                float2 hi = {c2 * scale, c3 * scale};
                *reinterpret_cast<float2*>(Cp + (long long)row * N + col)       = lo;
                *reinterpret_cast<float2*>(Cp + (long long)(row + 8) * N + col) = hi;
            } else if (mode == 2) {
                __half* Cp = reinterpret_cast<__half*>(C) + sC * blockIdx.z;
                *reinterpret_cast<__half2*>(Cp + (long long)row * N + col) =
                    __floats2half2_rn(c0 * scale, c1 * scale);
                *reinterpret_cast<__half2*>(Cp + (long long)(row + 8) * N + col) =
                    __floats2half2_rn(c2 * scale, c3 * scale);
            } else {
                const int bb = row >> 12;
                const int ss = row & 4095;
                const long long base = (long long)bb << 22;
                const float b0 = bias[col], b1 = bias[col + 1];
                if (region == 0) {
                    __half2 lo = __floats2half2_rn((c0 + b0) * 0.03125f, (c1 + b1) * 0.03125f);
                    __half2 hi = __floats2half2_rn((c2 + b0) * 0.03125f, (c3 + b1) * 0.03125f);
                    __half* dst = g_q + base + (long long)ss * 1024 + col;
                    *reinterpret_cast<__half2*>(dst)        = lo;
                    *reinterpret_cast<__half2*>(dst + 8192) = hi;
                } else if (region == 1) {
                    __half2 lo = __floats2half2_rn(c0 + b0, c1 + b1);
                    __half2 hi = __floats2half2_rn(c2 + b0, c3 + b1);
                    __half* dst = g_k + base + (long long)ss * 1024 + (col - 1024);
                    *reinterpret_cast<__half2*>(dst)        = lo;
                    *reinterpret_cast<__half2*>(dst + 8192) = hi;
                } else {
                    const int d = col - 2048;
                    __half* vt = g_vt + base + ss;
                    vt[(long long)d * 4096]           = __float2half_rn(c0 + b0);
                    vt[(long long)(d + 1) * 4096]     = __float2half_rn(c1 + b1);
                    vt[(long long)d * 4096 + 8]       = __float2half_rn(c2 + b0);
                    vt[(long long)(d + 1) * 4096 + 8] = __float2half_rn(c3 + b1);
                }
            }
        }
    }
}

// Merged f32 -> fp16 convert of X (n8x float4-pairs) then W, streaming stores.
__global__ __launch_bounds__(256) void to_half2(__half* __restrict__ dx,
                                                const float* __restrict__ sx, int n8x,
                                                __half* __restrict__ dw,
                                                const float* __restrict__ sw, int n8w)
{
    int i = blockIdx.x * blockDim.x + threadIdx.x;
    const float* src; __half* dst; int j;
    if (i < n8x)            { src = sx; dst = dx; j = i; }
    else if (i < n8x + n8w) { src = sw; dst = dw; j = i - n8x; }
    else return;
    float4 a = __ldg(reinterpret_cast<const float4*>(src) + 2 * j);
    float4 b = __ldg(reinterpret_cast<const float4*>(src) + 2 * j + 1);
    __half2 h[4] = {__floats2half2_rn(a.x, a.y), __floats2half2_rn(a.z, a.w),
                    __floats2half2_rn(b.x, b.y), __floats2half2_rn(b.z, b.w)};
    __stcs(reinterpret_cast<uint4*>(dst) + j, *reinterpret_cast<uint4*>(h));
}

// One block per row: softmax over 4096 fp16 scores -> fp16 probs.
__global__ __launch_bounds__(256) void softmax_rows(const __half* __restrict__ S,
                                                    __half* __restrict__ P)
{
    const __half* p = S + (long long)blockIdx.x * 4096;
    __half* po      = P + (long long)blockIdx.x * 4096;
    const int tid  = threadIdx.x;
    const int warp = tid >> 5;
    const int lane = tid & 31;
    __shared__ float red[8];

    float v[16];
    #pragma unroll
    for (int u = 0; u < 2; u++) {
        uint4 raw = reinterpret_cast<const uint4*>(p)[tid * 2 + u];
        const uint32_t* rw = reinterpret_cast<const uint32_t*>(&raw);
        #pragma unroll
        for (int j = 0; j < 4; j++) {
            float2 f = __half22float2(*reinterpret_cast<const __half2*>(&rw[j]));
            v[u * 8 + j * 2]     = f.x;
            v[u * 8 + j * 2 + 1] = f.y;
        }
    }

    float m = -3.4e38f;
    #pragma unroll
    for (int j = 0; j < 16; j++) m = fmaxf(m, v[j]);
    #pragma unroll
    for (int o = 16; o > 0; o >>= 1) m = fmaxf(m, __shfl_xor_sync(0xffffffffu, m, o));
    if (lane == 0) red[warp] = m;
    __syncthreads();
    m = red[0];
    #pragma unroll
    for (int i = 1; i < 8; i++) m = fmaxf(m, red[i]);
    __syncthreads();

    float sum = 0.f;
    #pragma unroll
    for (int j = 0; j < 16; j++) { v[j] = __expf(v[j] - m); sum += v[j]; }
    #pragma unroll
    for (int o = 16; o > 0; o >>= 1) sum += __shfl_xor_sync(0xffffffffu, sum, o);
    if (lane == 0) red[warp] = sum;
    __syncthreads();
    sum = red[0] + red[1] + red[2] + red[3] + red[4] + red[5] + red[6] + red[7];

    const float inv = 1.0f / sum;
    #pragma unroll
    for (int u = 0; u < 2; u++) {
        __half2 h[4];
        #pragma unroll
        for (int j = 0; j < 4; j++)
            h[j] = __floats2half2_rn(v[u * 8 + j * 2] * inv, v[u * 8 + j * 2 + 1] * inv);
        __stcs(reinterpret_cast<uint4*>(po) + tid * 2 + u, *reinterpret_cast<uint4*>(h));
    }
}

extern "C" void kernel_launch(void* const* d_in, const int* in_sizes, int n_in,
                              void* d_out, int out_size)
{
    const float* X    = (const float*)d_in[0];
    const float* W    = (const float*)d_in[1];
    const float* bias = (const float*)d_in[2];
    float*       out  = (float*)d_out;

    __half *x, *w, *q, *k, *vt, *s, *pp;
    cudaGetSymbolAddress((void**)&x,  g_x);
    cudaGetSymbolAddress((void**)&w,  g_w);
    cudaGetSymbolAddress((void**)&q,  g_q);
    cudaGetSymbolAddress((void**)&k,  g_k);
    cudaGetSymbolAddress((void**)&vt, g_vt);
    cudaGetSymbolAddress((void**)&s,  g_s);
    cudaGetSymbolAddress((void**)&pp, g_p);

    static int once = 0;
    if (!once) {
        cudaFuncSetAttribute(gemm_tc, cudaFuncAttributeMaxDynamicSharedMemorySize, 98304);
        once = 1;
    }

    // 0) convert X and W to fp16 (one launch)
    to_half2<<<(2097152 + 393216 + 255) / 256, 256>>>(x, X, 2097152, w, W, 393216);

    // 1) QKV projection -> route Q/32, K, Vt (all fp16)
    gemm_tc<<<dim3(24, 128, 1), 256, 98304>>>(x, w, bias, nullptr,
                                              1024, 3072, 1024, 1024,
                                              0, 0, 0,
                                              /*mode=*/0, 1.0f);
    // 2) Scores (fp16 out): per-batch [4096,1024] @ [4096,1024]^T
    gemm_tc<<<dim3(32, 32, 4), 256, 98304>>>(q, k, bias, (float*)s,
                                             1024, 4096, 1024, 1024,
                                             1LL << 22, 1LL << 22, 1LL << 24,
                                             /*mode=*/2, 1.0f);
    // 3) Row softmax fp16 -> fp16 probs
    softmax_rows<<<16384, 256>>>(s, pp);
    // 4) Output: per-batch [4096,4096] @ [1024,4096]^T -> fp32 out
    gemm_tc<<<dim3(8, 32, 4), 256, 98304>>>(pp, vt, bias, out,
                                            4096, 1024, 4096, 4096,
                                            1LL << 24, 1LL << 22, 1LL << 22,
                                            /*mode=*/1, 1.0f);
}